// round 9
// baseline (speedup 1.0000x reference)
#include <cuda_runtime.h>
#include <cuda_fp16.h>
#include <math.h>
#include <stdint.h>

// Problem constants
#define D_MODEL 768
#define NHEAD   12
#define DK      64
#define BATCH   2
#define SEQ     2048
#define MROWS   (BATCH*SEQ)   // 4096
#define N1 (MROWS*D_MODEL)    // 3,145,728
#define N2 (D_MODEL*D_MODEL)  // 589,824

// Scratch in device globals (allocation-free rule)
__device__ __half g_xh[3 * N1];    // half copies of q,k,v inputs
__device__ __half g_wh[4 * N2];    // half copies of w_q,w_k,w_v,w_o
__device__ __half g_ph[3 * N1];    // projected qh, kh, vh (half)
__device__ __half g_ctxh[N1];      // attention context (half)
__device__ float  g_attn[(size_t)BATCH * NHEAD * SEQ * SEQ]; // fallback

// ---------------------------------------------------------------------------
// Low-level helpers
// ---------------------------------------------------------------------------
__device__ __forceinline__ uint32_t packh2(float x, float y) {
    __half2 h = __floats2half2_rn(x, y);
    return *reinterpret_cast<uint32_t*>(&h);
}

__device__ __forceinline__ void mma_f16(float* d, const uint32_t* a, const uint32_t* b) {
    asm volatile(
        "mma.sync.aligned.m16n8k16.row.col.f32.f16.f16.f32 "
        "{%0,%1,%2,%3}, {%4,%5,%6,%7}, {%8,%9}, {%0,%1,%2,%3};\n"
        : "+f"(d[0]), "+f"(d[1]), "+f"(d[2]), "+f"(d[3])
        : "r"(a[0]), "r"(a[1]), "r"(a[2]), "r"(a[3]), "r"(b[0]), "r"(b[1]));
}

__device__ __forceinline__ void ldsm_x4(uint32_t* r, const void* p) {
    uint32_t a = (uint32_t)__cvta_generic_to_shared(p);
    asm volatile("ldmatrix.sync.aligned.m8n8.x4.shared.b16 {%0,%1,%2,%3}, [%4];"
                 : "=r"(r[0]), "=r"(r[1]), "=r"(r[2]), "=r"(r[3]) : "r"(a));
}
__device__ __forceinline__ void ldsm_x4_t(uint32_t* r, const void* p) {
    uint32_t a = (uint32_t)__cvta_generic_to_shared(p);
    asm volatile("ldmatrix.sync.aligned.m8n8.x4.trans.shared.b16 {%0,%1,%2,%3}, [%4];"
                 : "=r"(r[0]), "=r"(r[1]), "=r"(r[2]), "=r"(r[3]) : "r"(a));
}

__device__ __forceinline__ void cp16(void* s, const void* g) {
    uint32_t a = (uint32_t)__cvta_generic_to_shared(s);
    asm volatile("cp.async.cg.shared.global [%0], [%1], 16;" :: "r"(a), "l"(g));
}
__device__ __forceinline__ void cp_commit() {
    asm volatile("cp.async.commit_group;" ::);
}
__device__ __forceinline__ void cp_wait1() {
    asm volatile("cp.async.wait_group 1;" ::);
}
__device__ __forceinline__ void cp_wait0() {
    asm volatile("cp.async.wait_group 0;" ::);
}

// ---------------------------------------------------------------------------
// Convert kernel: fp32 inputs/weights -> half scratch
// ---------------------------------------------------------------------------
__global__ void convert_kernel(const float* __restrict__ q, const float* __restrict__ k,
                               const float* __restrict__ v,
                               const float* __restrict__ wq, const float* __restrict__ wk,
                               const float* __restrict__ wv, const float* __restrict__ wo)
{
    const long long TOT4 = (3LL * N1 + 4LL * N2) / 4;
    for (long long i4 = blockIdx.x * blockDim.x + threadIdx.x; i4 < TOT4;
         i4 += (long long)gridDim.x * blockDim.x) {
        const long long e = i4 * 4;
        const float* src;
        __half* dst;
        if (e < 3LL * N1) {
            const int w = (int)(e / N1);
            const long long off = e - (long long)w * N1;
            src = (w == 0 ? q : w == 1 ? k : v) + off;
            dst = g_xh + e;
        } else {
            const long long e2 = e - 3LL * N1;
            const int w = (int)(e2 / N2);
            const long long off = e2 - (long long)w * N2;
            src = (w == 0 ? wq : w == 1 ? wk : w == 2 ? wv : wo) + off;
            dst = g_wh + e2;
        }
        const float4 f = *(const float4*)src;
        uint2 u;
        u.x = packh2(f.x, f.y);
        u.y = packh2(f.z, f.w);
        *(uint2*)dst = u;
    }
}

// ---------------------------------------------------------------------------
// 768-K GEMM body: C = A_h[4096x768] @ W_h[768x768] + bias
// Block 128x64, BK=32, cp.async double-buffer, ldmatrix fragments. 256 thr.
// ---------------------------------------------------------------------------
template <bool HALF_OUT>
__device__ __forceinline__ void gemm768_body(const __half* __restrict__ A,
                                             const __half* __restrict__ W,
                                             const float* __restrict__ bias,
                                             void* __restrict__ C)
{
    __shared__ alignas(16) __half As[2][128][40];
    __shared__ alignas(16) __half Ws[2][32][72];

    const int tid  = threadIdx.x;
    const int warp = tid >> 5;
    const int lane = tid & 31;
    const int gid  = lane >> 2;
    const int tig  = lane & 3;
    const int wm   = (warp & 3) * 32;
    const int wn   = (warp >> 2) * 32;
    const int lrow = lane & 15;
    const int lcol = (lane >> 4) << 3;

    const int m0 = blockIdx.y * 128;
    const int n0 = blockIdx.x * 64;
    const __half* Ab = A + (long long)m0 * D_MODEL;
    const __half* Wb = W + n0;

    auto issueA = [&](int s, int k0) {
        #pragma unroll
        for (int it = 0; it < 2; it++) {
            const int c = tid + it * 256;
            const int row = c >> 2;
            const int ch  = (c & 3) * 8;
            cp16(&As[s][row][ch], Ab + (long long)row * D_MODEL + k0 + ch);
        }
    };
    auto issueW = [&](int s, int k0) {
        const int row = tid >> 3;
        const int ch  = (tid & 7) * 8;
        cp16(&Ws[s][row][ch], Wb + (long long)(k0 + row) * D_MODEL + ch);
    };

    issueA(0, 0);
    issueW(0, 0);
    cp_commit();

    float acc[2][4][4] = {};

    for (int s = 0; s < 24; s++) {
        if (s < 23) {
            issueA((s + 1) & 1, (s + 1) * 32);
            issueW((s + 1) & 1, (s + 1) * 32);
            cp_commit();
            cp_wait1();
        } else {
            cp_wait0();
        }
        __syncthreads();

        const int bb = s & 1;
        #pragma unroll
        for (int kk = 0; kk < 32; kk += 16) {
            uint32_t af[2][4], bt[2][4];
            ldsm_x4(af[0], &As[bb][wm + lrow][kk + lcol]);
            ldsm_x4(af[1], &As[bb][wm + 16 + lrow][kk + lcol]);
            ldsm_x4_t(bt[0], &Ws[bb][kk + lrow][wn + lcol]);
            ldsm_x4_t(bt[1], &Ws[bb][kk + lrow][wn + 16 + lcol]);
            #pragma unroll
            for (int i = 0; i < 2; i++) {
                mma_f16(acc[i][0], af[i], &bt[0][0]);
                mma_f16(acc[i][1], af[i], &bt[0][2]);
                mma_f16(acc[i][2], af[i], &bt[1][0]);
                mma_f16(acc[i][3], af[i], &bt[1][2]);
            }
        }
        __syncthreads();
    }

    #pragma unroll
    for (int i = 0; i < 2; i++) {
        const int row = m0 + wm + 16 * i + gid;
        #pragma unroll
        for (int j = 0; j < 4; j++) {
            const int col = n0 + wn + 8 * j + 2 * tig;
            const float b0 = bias[col];
            const float b1 = bias[col + 1];
            const float v0 = acc[i][j][0] + b0;
            const float v1 = acc[i][j][1] + b1;
            const float v2 = acc[i][j][2] + b0;
            const float v3 = acc[i][j][3] + b1;
            if (HALF_OUT) {
                __half* Ch = (__half*)C;
                *(uint32_t*)(Ch + (long long)row * D_MODEL + col)       = packh2(v0, v1);
                *(uint32_t*)(Ch + (long long)(row + 8) * D_MODEL + col) = packh2(v2, v3);
            } else {
                float* Cf = (float*)C;
                *(float2*)(Cf + (long long)row * D_MODEL + col)       = make_float2(v0, v1);
                *(float2*)(Cf + (long long)(row + 8) * D_MODEL + col) = make_float2(v2, v3);
            }
        }
    }
}

__global__ __launch_bounds__(256, 3) void qkv_proj_kernel(
    const float* __restrict__ bq, const float* __restrict__ bk, const float* __restrict__ bv)
{
    const int z = blockIdx.z;
    const float* bias = (z == 0) ? bq : (z == 1) ? bk : bv;
    gemm768_body<true>(g_xh + (long long)z * N1, g_wh + (long long)z * N2,
                       bias, g_ph + (long long)z * N1);
}

__global__ __launch_bounds__(256, 3) void out_proj_kernel(
    const float* __restrict__ bo, float* __restrict__ out)
{
    gemm768_body<false>(g_ctxh, g_wh + 3LL * N2, bo, out);
}

// ---------------------------------------------------------------------------
// Fused attention: 512 threads = 16 warps (4M x 4N), warp tile 32x16.
// Per (z, 128-q tile):
//   pass 1: S = Q K^T (fp16 MMA), rowsum of exp(S/8) — no gmem writes
//   pass 2: recompute S, p = exp(S/8)*inv, write p to attn (only touch),
//           stash half(p) in smem, ctx += p @ V
// Accumulators: 16 regs score + 16 regs ctx -> fits 64-reg budget at
// launch_bounds(512,2) = 1024 threads/SM (2x round-7 warp parallelism).
// ---------------------------------------------------------------------------
struct SmemAttn {
    __half Qs[128][72];      // 18 KB, persists both passes
    __half Ks[2][64][72];    // 18 KB double-buffered
    __half Vs[2][64][72];    // 18 KB double-buffered (pass 2 only)
    __half Ps[128][72];      // 18 KB normalized p (pass 2)
    float  rowsum[128];
};

__global__ __launch_bounds__(512, 2) void fused_attn_kernel(float* __restrict__ attn)
{
    extern __shared__ char smraw[];
    SmemAttn& sm = *reinterpret_cast<SmemAttn*>(smraw);

    const int tid  = threadIdx.x;
    const int warp = tid >> 5;            // 0..15
    const int lane = tid & 31;
    const int gid  = lane >> 2;
    const int tig  = lane & 3;
    const int wm   = (warp & 3) * 32;     // M: 4 groups of 32 rows
    const int wn   = (warp >> 2) * 16;    // N: 4 groups of 16 cols
    const int lrow = lane & 15;
    const int lcol = (lane >> 4) << 3;

    const int q0 = blockIdx.x * 128;
    const int z  = blockIdx.y;
    const int b  = z / NHEAD;
    const int h  = z % NHEAD;

    const __half* qb = g_ph + (long long)b * SEQ * D_MODEL + h * DK;
    const __half* kb = g_ph + N1 + (long long)b * SEQ * D_MODEL + h * DK;
    const __half* vb = g_ph + 2LL * N1 + (long long)b * SEQ * D_MODEL + h * DK;
    float* ab = attn + (long long)z * SEQ * SEQ;
    __half* cb = g_ctxh + (long long)b * SEQ * D_MODEL + h * DK;

    auto issueK = [&](int s, int n0) {
        const int key = tid >> 3;          // 0..63
        const int ch  = (tid & 7) * 8;
        cp16(&sm.Ks[s][key][ch], kb + (long long)(n0 + key) * D_MODEL + ch);
    };
    auto issueV = [&](int s, int n0) {
        const int key = tid >> 3;
        const int ch  = (tid & 7) * 8;
        cp16(&sm.Vs[s][key][ch], vb + (long long)(n0 + key) * D_MODEL + ch);
    };

    // prologue: Q tile + K tile 0
    #pragma unroll
    for (int it = 0; it < 2; it++) {
        const int c = tid + it * 512;      // 0..1023
        const int row = c >> 3;
        const int ch  = (c & 7) * 8;
        cp16(&sm.Qs[row][ch], qb + (long long)(q0 + row) * D_MODEL + ch);
    }
    issueK(0, 0);
    cp_commit();
    if (tid < 128) sm.rowsum[tid] = 0.f;

    // =========================== PASS 1: rowsums ===========================
    for (int t = 0; t < 32; t++) {
        if (t < 31) {
            issueK((t + 1) & 1, (t + 1) * 64);
            cp_commit();
            cp_wait1();
        } else {
            cp_wait0();
        }
        __syncthreads();

        const int bb = t & 1;
        float sacc[2][2][4] = {};
        #pragma unroll
        for (int kk = 0; kk < 64; kk += 16) {
            uint32_t af[2][4], kf[4];
            ldsm_x4(af[0], &sm.Qs[wm + lrow][kk + lcol]);
            ldsm_x4(af[1], &sm.Qs[wm + 16 + lrow][kk + lcol]);
            ldsm_x4(kf, &sm.Ks[bb][wn + lrow][kk + lcol]);
            uint32_t b0[2] = { kf[0], kf[2] };
            uint32_t b1[2] = { kf[1], kf[3] };
            #pragma unroll
            for (int i = 0; i < 2; i++) {
                mma_f16(sacc[i][0], af[i], b0);
                mma_f16(sacc[i][1], af[i], b1);
            }
        }

        #pragma unroll
        for (int i = 0; i < 2; i++) {
            float s0 = 0.f, s1 = 0.f;
            #pragma unroll
            for (int j = 0; j < 2; j++) {
                s0 += __expf(sacc[i][j][0] * 0.125f) + __expf(sacc[i][j][1] * 0.125f);
                s1 += __expf(sacc[i][j][2] * 0.125f) + __expf(sacc[i][j][3] * 0.125f);
            }
            s0 += __shfl_xor_sync(0xffffffffu, s0, 1);
            s0 += __shfl_xor_sync(0xffffffffu, s0, 2);
            s1 += __shfl_xor_sync(0xffffffffu, s1, 1);
            s1 += __shfl_xor_sync(0xffffffffu, s1, 2);
            if (tig == 0) {
                atomicAdd(&sm.rowsum[wm + 16 * i + gid], s0);
                atomicAdd(&sm.rowsum[wm + 16 * i + gid + 8], s1);
            }
        }
        __syncthreads();
    }

    if (tid < 128) sm.rowsum[tid] = 1.0f / sm.rowsum[tid];
    __syncthreads();

    // hoist per-thread inverse rowsums
    float invr[2][2];
    #pragma unroll
    for (int i = 0; i < 2; i++) {
        invr[i][0] = sm.rowsum[wm + 16 * i + gid];
        invr[i][1] = sm.rowsum[wm + 16 * i + gid + 8];
    }

    // ================= PASS 2: recompute, write p, accumulate PV ===========
    issueK(0, 0);
    issueV(0, 0);
    cp_commit();

    float cacc[2][2][4] = {};

    for (int t = 0; t < 32; t++) {
        const int n0 = t * 64;
        if (t < 31) {
            issueK((t + 1) & 1, (t + 1) * 64);
            issueV((t + 1) & 1, (t + 1) * 64);
            cp_commit();
            cp_wait1();
        } else {
            cp_wait0();
        }
        __syncthreads();   // loads visible; prev iteration's PV done (Ps free)

        const int bb = t & 1;

        // scores recompute
        float sacc[2][2][4] = {};
        #pragma unroll
        for (int kk = 0; kk < 64; kk += 16) {
            uint32_t af[2][4], kf[4];
            ldsm_x4(af[0], &sm.Qs[wm + lrow][kk + lcol]);
            ldsm_x4(af[1], &sm.Qs[wm + 16 + lrow][kk + lcol]);
            ldsm_x4(kf, &sm.Ks[bb][wn + lrow][kk + lcol]);
            uint32_t b0[2] = { kf[0], kf[2] };
            uint32_t b1[2] = { kf[1], kf[3] };
            #pragma unroll
            for (int i = 0; i < 2; i++) {
                mma_f16(sacc[i][0], af[i], b0);
                mma_f16(sacc[i][1], af[i], b1);
            }
        }

        // normalized p: write to attn (only gmem touch) + stash half in Ps
        #pragma unroll
        for (int i = 0; i < 2; i++) {
            const int r = wm + 16 * i + gid;
            const float inv0 = invr[i][0];
            const float inv1 = invr[i][1];
            #pragma unroll
            for (int j = 0; j < 2; j++) {
                const int cl = wn + 8 * j + 2 * tig;
                float2 e01, e23;
                e01.x = __expf(sacc[i][j][0] * 0.125f) * inv0;
                e01.y = __expf(sacc[i][j][1] * 0.125f) * inv0;
                e23.x = __expf(sacc[i][j][2] * 0.125f) * inv1;
                e23.y = __expf(sacc[i][j][3] * 0.125f) * inv1;
                *(float2*)(ab + (long long)(q0 + r) * SEQ + n0 + cl)     = e01;
                *(float2*)(ab + (long long)(q0 + r + 8) * SEQ + n0 + cl) = e23;
                *(uint32_t*)&sm.Ps[r][cl]     = packh2(e01.x, e01.y);
                *(uint32_t*)&sm.Ps[r + 8][cl] = packh2(e23.x, e23.y);
            }
        }
        __syncthreads();   // Ps visible to all warps

        // PV MMA: ctx += P @ V  (warp's dk cols = wn..wn+16)
        #pragma unroll
        for (int kk = 0; kk < 64; kk += 16) {
            uint32_t af[2][4], vt[4];
            ldsm_x4(af[0], &sm.Ps[wm + lrow][kk + lcol]);
            ldsm_x4(af[1], &sm.Ps[wm + 16 + lrow][kk + lcol]);
            ldsm_x4_t(vt, &sm.Vs[bb][kk + lrow][wn + lcol]);
            #pragma unroll
            for (int i = 0; i < 2; i++) {
                mma_f16(cacc[i][0], af[i], &vt[0]);
                mma_f16(cacc[i][1], af[i], &vt[2]);
            }
        }
        __syncthreads();   // Ks/Vs[bb] free for next iteration's prefetch
    }

    // ctx epilogue (half)
    #pragma unroll
    for (int i = 0; i < 2; i++) {
        const int row = q0 + wm + 16 * i + gid;
        #pragma unroll
        for (int j = 0; j < 2; j++) {
            const int col = wn + 8 * j + 2 * tig;
            *(uint32_t*)(cb + (long long)row * D_MODEL + col)       = packh2(cacc[i][j][0], cacc[i][j][1]);
            *(uint32_t*)(cb + (long long)(row + 8) * D_MODEL + col) = packh2(cacc[i][j][2], cacc[i][j][3]);
        }
    }
}

// ---------------------------------------------------------------------------
extern "C" void kernel_launch(void* const* d_in, const int* in_sizes, int n_in,
                              void* d_out, int out_size)
{
    const float* q   = (const float*)d_in[0];
    const float* k   = (const float*)d_in[1];
    const float* v   = (const float*)d_in[2];
    const float* w_q = (const float*)d_in[3];
    const float* b_q = (const float*)d_in[4];
    const float* w_k = (const float*)d_in[5];
    const float* b_k = (const float*)d_in[6];
    const float* w_v = (const float*)d_in[7];
    const float* b_v = (const float*)d_in[8];
    const float* w_o = (const float*)d_in[9];
    const float* b_o = (const float*)d_in[10];

    float* gattn;
    cudaGetSymbolAddress((void**)&gattn, g_attn);

    float* outp = (float*)d_out;
    const long long OUT_ELEMS  = (long long)MROWS * D_MODEL;
    const long long ATTN_ELEMS = (long long)BATCH * NHEAD * SEQ * SEQ;
    float* attn = ((long long)out_size >= OUT_ELEMS + ATTN_ELEMS) ? (outp + OUT_ELEMS)
                                                                  : gattn;

    // 0. convert inputs + weights to half
    convert_kernel<<<1024, 256>>>(q, k, v, w_q, w_k, w_v, w_o);

    // 1. QKV projections (half in, half out)
    {
        const dim3 grid(D_MODEL / 64, MROWS / 128, 3);
        qkv_proj_kernel<<<grid, 256>>>(b_q, b_k, b_v);
    }

    // 2. fused attention (scores + softmax + attn write + PV)
    {
        static int smem_set = 0;
        const int smem_bytes = (int)sizeof(SmemAttn);
        if (!smem_set) {
            cudaFuncSetAttribute(fused_attn_kernel,
                                 cudaFuncAttributeMaxDynamicSharedMemorySize, smem_bytes);
            smem_set = 1;
        }
        const dim3 grid(SEQ / 128, BATCH * NHEAD);
        fused_attn_kernel<<<grid, 512, smem_bytes>>>(attn);
    }

    // 3. output projection (fp32 out)
    {
        const dim3 grid(D_MODEL / 64, MROWS / 128, 1);
        out_proj_kernel<<<grid, 256>>>(b_o, outp);
    }
}

// round 10
// speedup vs baseline: 1.1002x; 1.1002x over previous
#include <cuda_runtime.h>
#include <cuda_fp16.h>
#include <math.h>
#include <stdint.h>

// Problem constants
#define D_MODEL 768
#define NHEAD   12
#define DK      64
#define BATCH   2
#define SEQ     2048
#define MROWS   (BATCH*SEQ)   // 4096
#define N1 (MROWS*D_MODEL)    // 3,145,728
#define N2 (D_MODEL*D_MODEL)  // 589,824

// Scratch in device globals (allocation-free rule)
__device__ __half g_xh[3 * N1];    // half copies of q,k,v inputs
__device__ __half g_wh[4 * N2];    // half copies of w_q,w_k,w_v,w_o
__device__ __half g_ph[3 * N1];    // projected qh, kh, vh (half)
__device__ __half g_ctxh[N1];      // attention context (half)
__device__ float  g_attn[(size_t)BATCH * NHEAD * SEQ * SEQ]; // fallback

// ---------------------------------------------------------------------------
// Low-level helpers
// ---------------------------------------------------------------------------
__device__ __forceinline__ uint32_t packh2(float x, float y) {
    __half2 h = __floats2half2_rn(x, y);
    return *reinterpret_cast<uint32_t*>(&h);
}

__device__ __forceinline__ void mma_f16(float* d, const uint32_t* a, const uint32_t* b) {
    asm volatile(
        "mma.sync.aligned.m16n8k16.row.col.f32.f16.f16.f32 "
        "{%0,%1,%2,%3}, {%4,%5,%6,%7}, {%8,%9}, {%0,%1,%2,%3};\n"
        : "+f"(d[0]), "+f"(d[1]), "+f"(d[2]), "+f"(d[3])
        : "r"(a[0]), "r"(a[1]), "r"(a[2]), "r"(a[3]), "r"(b[0]), "r"(b[1]));
}

__device__ __forceinline__ void ldsm_x4(uint32_t* r, const void* p) {
    uint32_t a = (uint32_t)__cvta_generic_to_shared(p);
    asm volatile("ldmatrix.sync.aligned.m8n8.x4.shared.b16 {%0,%1,%2,%3}, [%4];"
                 : "=r"(r[0]), "=r"(r[1]), "=r"(r[2]), "=r"(r[3]) : "r"(a));
}
__device__ __forceinline__ void ldsm_x4_t(uint32_t* r, const void* p) {
    uint32_t a = (uint32_t)__cvta_generic_to_shared(p);
    asm volatile("ldmatrix.sync.aligned.m8n8.x4.trans.shared.b16 {%0,%1,%2,%3}, [%4];"
                 : "=r"(r[0]), "=r"(r[1]), "=r"(r[2]), "=r"(r[3]) : "r"(a));
}

__device__ __forceinline__ void cp16(void* s, const void* g) {
    uint32_t a = (uint32_t)__cvta_generic_to_shared(s);
    asm volatile("cp.async.cg.shared.global [%0], [%1], 16;" :: "r"(a), "l"(g));
}
__device__ __forceinline__ void cp_commit() {
    asm volatile("cp.async.commit_group;" ::);
}
__device__ __forceinline__ void cp_wait1() {
    asm volatile("cp.async.wait_group 1;" ::);
}
__device__ __forceinline__ void cp_wait0() {
    asm volatile("cp.async.wait_group 0;" ::);
}

// ---------------------------------------------------------------------------
// Convert kernel: fp32 inputs/weights -> half scratch
// ---------------------------------------------------------------------------
__global__ void convert_kernel(const float* __restrict__ q, const float* __restrict__ k,
                               const float* __restrict__ v,
                               const float* __restrict__ wq, const float* __restrict__ wk,
                               const float* __restrict__ wv, const float* __restrict__ wo)
{
    const long long TOT4 = (3LL * N1 + 4LL * N2) / 4;
    for (long long i4 = blockIdx.x * blockDim.x + threadIdx.x; i4 < TOT4;
         i4 += (long long)gridDim.x * blockDim.x) {
        const long long e = i4 * 4;
        const float* src;
        __half* dst;
        if (e < 3LL * N1) {
            const int w = (int)(e / N1);
            const long long off = e - (long long)w * N1;
            src = (w == 0 ? q : w == 1 ? k : v) + off;
            dst = g_xh + e;
        } else {
            const long long e2 = e - 3LL * N1;
            const int w = (int)(e2 / N2);
            const long long off = e2 - (long long)w * N2;
            src = (w == 0 ? wq : w == 1 ? wk : w == 2 ? wv : wo) + off;
            dst = g_wh + e2;
        }
        const float4 f = *(const float4*)src;
        uint2 u;
        u.x = packh2(f.x, f.y);
        u.y = packh2(f.z, f.w);
        *(uint2*)dst = u;
    }
}

// ---------------------------------------------------------------------------
// 768-K GEMM body: C = A_h[4096x768] @ W_h[768x768] + bias
// Block tile 128x128, BK=32, cp.async double-buffer, ldmatrix fragments.
// 256 threads = 8 warps (4M x 2N), warp tile 32x64 (acc 64 regs).
// ---------------------------------------------------------------------------
template <bool HALF_OUT>
__device__ __forceinline__ void gemm768_body(const __half* __restrict__ A,
                                             const __half* __restrict__ W,
                                             const float* __restrict__ bias,
                                             void* __restrict__ C)
{
    __shared__ alignas(16) __half As[2][128][40];
    __shared__ alignas(16) __half Ws[2][32][136];

    const int tid  = threadIdx.x;
    const int warp = tid >> 5;
    const int lane = tid & 31;
    const int gid  = lane >> 2;
    const int tig  = lane & 3;
    const int wm   = (warp & 3) * 32;      // M: 4 groups of 32
    const int wn   = (warp >> 2) * 64;     // N: 2 groups of 64
    const int lrow = lane & 15;
    const int lcol = (lane >> 4) << 3;

    const int m0 = blockIdx.y * 128;
    const int n0 = blockIdx.x * 128;
    const __half* Ab = A + (long long)m0 * D_MODEL;
    const __half* Wb = W + n0;

    auto issueA = [&](int s, int k0) {
        #pragma unroll
        for (int it = 0; it < 2; it++) {
            const int c = tid + it * 256;        // 0..511
            const int row = c >> 2;              // 0..127
            const int ch  = (c & 3) * 8;         // 0..24
            cp16(&As[s][row][ch], Ab + (long long)row * D_MODEL + k0 + ch);
        }
    };
    auto issueW = [&](int s, int k0) {
        #pragma unroll
        for (int it = 0; it < 2; it++) {
            const int c = tid + it * 256;        // 0..511
            const int row = c >> 4;              // 0..31
            const int ch  = (c & 15) * 8;        // 0..120
            cp16(&Ws[s][row][ch], Wb + (long long)(k0 + row) * D_MODEL + ch);
        }
    };

    issueA(0, 0);
    issueW(0, 0);
    cp_commit();

    float acc[2][8][4] = {};

    for (int s = 0; s < 24; s++) {
        if (s < 23) {
            issueA((s + 1) & 1, (s + 1) * 32);
            issueW((s + 1) & 1, (s + 1) * 32);
            cp_commit();
            cp_wait1();
        } else {
            cp_wait0();
        }
        __syncthreads();

        const int bb = s & 1;
        #pragma unroll
        for (int kk = 0; kk < 32; kk += 16) {
            uint32_t af[2][4], bt[4][4];
            ldsm_x4(af[0], &As[bb][wm + lrow][kk + lcol]);
            ldsm_x4(af[1], &As[bb][wm + 16 + lrow][kk + lcol]);
            #pragma unroll
            for (int jj = 0; jj < 4; jj++)
                ldsm_x4_t(bt[jj], &Ws[bb][kk + lrow][wn + 16 * jj + lcol]);
            #pragma unroll
            for (int i = 0; i < 2; i++)
                #pragma unroll
                for (int jj = 0; jj < 4; jj++) {
                    mma_f16(acc[i][2 * jj],     af[i], &bt[jj][0]);
                    mma_f16(acc[i][2 * jj + 1], af[i], &bt[jj][2]);
                }
        }
        __syncthreads();
    }

    #pragma unroll
    for (int i = 0; i < 2; i++) {
        const int row = m0 + wm + 16 * i + gid;
        #pragma unroll
        for (int j = 0; j < 8; j++) {
            const int col = n0 + wn + 8 * j + 2 * tig;
            const float b0 = bias[col];
            const float b1 = bias[col + 1];
            const float v0 = acc[i][j][0] + b0;
            const float v1 = acc[i][j][1] + b1;
            const float v2 = acc[i][j][2] + b0;
            const float v3 = acc[i][j][3] + b1;
            if (HALF_OUT) {
                __half* Ch = (__half*)C;
                *(uint32_t*)(Ch + (long long)row * D_MODEL + col)       = packh2(v0, v1);
                *(uint32_t*)(Ch + (long long)(row + 8) * D_MODEL + col) = packh2(v2, v3);
            } else {
                float* Cf = (float*)C;
                *(float2*)(Cf + (long long)row * D_MODEL + col)       = make_float2(v0, v1);
                *(float2*)(Cf + (long long)(row + 8) * D_MODEL + col) = make_float2(v2, v3);
            }
        }
    }
}

__global__ __launch_bounds__(256, 2) void qkv_proj_kernel(
    const float* __restrict__ bq, const float* __restrict__ bk, const float* __restrict__ bv)
{
    const int z = blockIdx.z;
    const float* bias = (z == 0) ? bq : (z == 1) ? bk : bv;
    gemm768_body<true>(g_xh + (long long)z * N1, g_wh + (long long)z * N2,
                       bias, g_ph + (long long)z * N1);
}

__global__ __launch_bounds__(256, 2) void out_proj_kernel(
    const float* __restrict__ bo, float* __restrict__ out)
{
    gemm768_body<false>(g_ctxh, g_wh + 3LL * N2, bo, out);
}

// ---------------------------------------------------------------------------
// Fused attention (round-7 configuration, verbatim): 256 threads, occ 2.
// Per (z, 128-q tile):
//   pass 1: S = Q K^T (fp16 MMA), rowsum of exp(S/8) — no gmem writes
//   pass 2: recompute S, p = exp(S/8)*inv, write p to attn (only touch),
//           stash half(p) in smem, ctx += p @ V
// ---------------------------------------------------------------------------
struct SmemAttn {
    __half Qs[128][72];      // 18 KB, persists both passes
    __half Ks[2][64][72];    // 18 KB double-buffered
    __half Vs[2][64][72];    // 18 KB double-buffered (pass 2 only)
    __half Ps[128][72];      // 18 KB normalized p (pass 2)
    float  rowsum[128];
};

__global__ __launch_bounds__(256, 2) void fused_attn_kernel(float* __restrict__ attn)
{
    extern __shared__ char smraw[];
    SmemAttn& sm = *reinterpret_cast<SmemAttn*>(smraw);

    const int tid  = threadIdx.x;
    const int warp = tid >> 5;
    const int lane = tid & 31;
    const int gid  = lane >> 2;
    const int tig  = lane & 3;
    const int wm   = (warp & 3) * 32;
    const int wn   = (warp >> 2) * 32;
    const int lrow = lane & 15;
    const int lcol = (lane >> 4) << 3;

    const int q0 = blockIdx.x * 128;
    const int z  = blockIdx.y;
    const int b  = z / NHEAD;
    const int h  = z % NHEAD;

    const __half* qb = g_ph + (long long)b * SEQ * D_MODEL + h * DK;
    const __half* kb = g_ph + N1 + (long long)b * SEQ * D_MODEL + h * DK;
    const __half* vb = g_ph + 2LL * N1 + (long long)b * SEQ * D_MODEL + h * DK;
    float* ab = attn + (long long)z * SEQ * SEQ;
    __half* cb = g_ctxh + (long long)b * SEQ * D_MODEL + h * DK;

    auto issueK = [&](int s, int n0) {
        #pragma unroll
        for (int it = 0; it < 2; it++) {
            const int c = tid + it * 256;
            const int key = c >> 3;
            const int ch  = (c & 7) * 8;
            cp16(&sm.Ks[s][key][ch], kb + (long long)(n0 + key) * D_MODEL + ch);
        }
    };
    auto issueV = [&](int s, int n0) {
        #pragma unroll
        for (int it = 0; it < 2; it++) {
            const int c = tid + it * 256;
            const int key = c >> 3;
            const int ch  = (c & 7) * 8;
            cp16(&sm.Vs[s][key][ch], vb + (long long)(n0 + key) * D_MODEL + ch);
        }
    };

    // prologue: Q tile + K tile 0
    #pragma unroll
    for (int it = 0; it < 4; it++) {
        const int c = tid + it * 256;
        const int row = c >> 3;
        const int ch  = (c & 7) * 8;
        cp16(&sm.Qs[row][ch], qb + (long long)(q0 + row) * D_MODEL + ch);
    }
    issueK(0, 0);
    cp_commit();
    if (tid < 128) sm.rowsum[tid] = 0.f;

    // =========================== PASS 1: rowsums ===========================
    for (int t = 0; t < 32; t++) {
        if (t < 31) {
            issueK((t + 1) & 1, (t + 1) * 64);
            cp_commit();
            cp_wait1();
        } else {
            cp_wait0();
        }
        __syncthreads();

        const int bb = t & 1;
        float sacc[2][4][4] = {};
        #pragma unroll
        for (int kk = 0; kk < 64; kk += 16) {
            uint32_t af[2][4], kf[2][4];
            ldsm_x4(af[0], &sm.Qs[wm + lrow][kk + lcol]);
            ldsm_x4(af[1], &sm.Qs[wm + 16 + lrow][kk + lcol]);
            ldsm_x4(kf[0], &sm.Ks[bb][wn + lrow][kk + lcol]);
            ldsm_x4(kf[1], &sm.Ks[bb][wn + 16 + lrow][kk + lcol]);
            uint32_t b0[2] = { kf[0][0], kf[0][2] };
            uint32_t b1[2] = { kf[0][1], kf[0][3] };
            uint32_t b2[2] = { kf[1][0], kf[1][2] };
            uint32_t b3[2] = { kf[1][1], kf[1][3] };
            #pragma unroll
            for (int i = 0; i < 2; i++) {
                mma_f16(sacc[i][0], af[i], b0);
                mma_f16(sacc[i][1], af[i], b1);
                mma_f16(sacc[i][2], af[i], b2);
                mma_f16(sacc[i][3], af[i], b3);
            }
        }

        #pragma unroll
        for (int i = 0; i < 2; i++) {
            const int r = wm + 16 * i + gid;
            float s0 = 0.f, s1 = 0.f;
            #pragma unroll
            for (int j = 0; j < 4; j++) {
                s0 += __expf(sacc[i][j][0] * 0.125f) + __expf(sacc[i][j][1] * 0.125f);
                s1 += __expf(sacc[i][j][2] * 0.125f) + __expf(sacc[i][j][3] * 0.125f);
            }
            s0 += __shfl_xor_sync(0xffffffffu, s0, 1);
            s0 += __shfl_xor_sync(0xffffffffu, s0, 2);
            s1 += __shfl_xor_sync(0xffffffffu, s1, 1);
            s1 += __shfl_xor_sync(0xffffffffu, s1, 2);
            if (tig == 0) {
                atomicAdd(&sm.rowsum[r], s0);
                atomicAdd(&sm.rowsum[r + 8], s1);
            }
        }
        __syncthreads();
    }

    if (tid < 128) sm.rowsum[tid] = 1.0f / sm.rowsum[tid];
    __syncthreads();

    // hoist per-thread inverse rowsums
    float invr[2][2];
    #pragma unroll
    for (int i = 0; i < 2; i++) {
        invr[i][0] = sm.rowsum[wm + 16 * i + gid];
        invr[i][1] = sm.rowsum[wm + 16 * i + gid + 8];
    }

    // ================= PASS 2: recompute, write p, accumulate PV ===========
    issueK(0, 0);
    issueV(0, 0);
    cp_commit();

    float cacc[2][4][4] = {};

    for (int t = 0; t < 32; t++) {
        const int n0 = t * 64;
        if (t < 31) {
            issueK((t + 1) & 1, (t + 1) * 64);
            issueV((t + 1) & 1, (t + 1) * 64);
            cp_commit();
            cp_wait1();
        } else {
            cp_wait0();
        }
        __syncthreads();   // loads visible; prev iteration's PV done (Ps free)

        const int bb = t & 1;

        // scores recompute
        float sacc[2][4][4] = {};
        #pragma unroll
        for (int kk = 0; kk < 64; kk += 16) {
            uint32_t af[2][4], kf[2][4];
            ldsm_x4(af[0], &sm.Qs[wm + lrow][kk + lcol]);
            ldsm_x4(af[1], &sm.Qs[wm + 16 + lrow][kk + lcol]);
            ldsm_x4(kf[0], &sm.Ks[bb][wn + lrow][kk + lcol]);
            ldsm_x4(kf[1], &sm.Ks[bb][wn + 16 + lrow][kk + lcol]);
            uint32_t b0[2] = { kf[0][0], kf[0][2] };
            uint32_t b1[2] = { kf[0][1], kf[0][3] };
            uint32_t b2[2] = { kf[1][0], kf[1][2] };
            uint32_t b3[2] = { kf[1][1], kf[1][3] };
            #pragma unroll
            for (int i = 0; i < 2; i++) {
                mma_f16(sacc[i][0], af[i], b0);
                mma_f16(sacc[i][1], af[i], b1);
                mma_f16(sacc[i][2], af[i], b2);
                mma_f16(sacc[i][3], af[i], b3);
            }
        }

        // normalized p: write to attn (only gmem touch) + stash half in Ps
        #pragma unroll
        for (int i = 0; i < 2; i++) {
            const int r = wm + 16 * i + gid;
            const float inv0 = invr[i][0];
            const float inv1 = invr[i][1];
            #pragma unroll
            for (int j = 0; j < 4; j++) {
                const int cl = wn + 8 * j + 2 * tig;
                float2 e01, e23;
                e01.x = __expf(sacc[i][j][0] * 0.125f) * inv0;
                e01.y = __expf(sacc[i][j][1] * 0.125f) * inv0;
                e23.x = __expf(sacc[i][j][2] * 0.125f) * inv1;
                e23.y = __expf(sacc[i][j][3] * 0.125f) * inv1;
                *(float2*)(ab + (long long)(q0 + r) * SEQ + n0 + cl)     = e01;
                *(float2*)(ab + (long long)(q0 + r + 8) * SEQ + n0 + cl) = e23;
                *(uint32_t*)&sm.Ps[r][cl]     = packh2(e01.x, e01.y);
                *(uint32_t*)&sm.Ps[r + 8][cl] = packh2(e23.x, e23.y);
            }
        }
        __syncthreads();   // Ps visible to all warps

        // PV MMA: ctx += P @ V
        #pragma unroll
        for (int kk = 0; kk < 64; kk += 16) {
            uint32_t af[2][4], vt[2][4];
            ldsm_x4(af[0], &sm.Ps[wm + lrow][kk + lcol]);
            ldsm_x4(af[1], &sm.Ps[wm + 16 + lrow][kk + lcol]);
            ldsm_x4_t(vt[0], &sm.Vs[bb][kk + lrow][wn + lcol]);
            ldsm_x4_t(vt[1], &sm.Vs[bb][kk + lrow][wn + 16 + lcol]);
            #pragma unroll
            for (int i = 0; i < 2; i++) {
                mma_f16(cacc[i][0], af[i], &vt[0][0]);
                mma_f16(cacc[i][1], af[i], &vt[0][2]);
                mma_f16(cacc[i][2], af[i], &vt[1][0]);
                mma_f16(cacc[i][3], af[i], &vt[1][2]);
            }
        }
        __syncthreads();   // Ks/Vs[bb] free for next iteration's prefetch
    }

    // ctx epilogue (half)
    #pragma unroll
    for (int i = 0; i < 2; i++) {
        const int row = q0 + wm + 16 * i + gid;
        #pragma unroll
        for (int j = 0; j < 4; j++) {
            const int col = wn + 8 * j + 2 * tig;
            *(uint32_t*)(cb + (long long)row * D_MODEL + col)       = packh2(cacc[i][j][0], cacc[i][j][1]);
            *(uint32_t*)(cb + (long long)(row + 8) * D_MODEL + col) = packh2(cacc[i][j][2], cacc[i][j][3]);
        }
    }
}

// ---------------------------------------------------------------------------
extern "C" void kernel_launch(void* const* d_in, const int* in_sizes, int n_in,
                              void* d_out, int out_size)
{
    const float* q   = (const float*)d_in[0];
    const float* k   = (const float*)d_in[1];
    const float* v   = (const float*)d_in[2];
    const float* w_q = (const float*)d_in[3];
    const float* b_q = (const float*)d_in[4];
    const float* w_k = (const float*)d_in[5];
    const float* b_k = (const float*)d_in[6];
    const float* w_v = (const float*)d_in[7];
    const float* b_v = (const float*)d_in[8];
    const float* w_o = (const float*)d_in[9];
    const float* b_o = (const float*)d_in[10];

    float* gattn;
    cudaGetSymbolAddress((void**)&gattn, g_attn);

    float* outp = (float*)d_out;
    const long long OUT_ELEMS  = (long long)MROWS * D_MODEL;
    const long long ATTN_ELEMS = (long long)BATCH * NHEAD * SEQ * SEQ;
    float* attn = ((long long)out_size >= OUT_ELEMS + ATTN_ELEMS) ? (outp + OUT_ELEMS)
                                                                  : gattn;

    // 0. convert inputs + weights to half
    convert_kernel<<<1024, 256>>>(q, k, v, w_q, w_k, w_v, w_o);

    // 1. QKV projections (half in, half out), 128x128 tiles
    {
        const dim3 grid(D_MODEL / 128, MROWS / 128, 3);
        qkv_proj_kernel<<<grid, 256>>>(b_q, b_k, b_v);
    }

    // 2. fused attention (scores + softmax + attn write + PV)
    {
        static int smem_set = 0;
        const int smem_bytes = (int)sizeof(SmemAttn);
        if (!smem_set) {
            cudaFuncSetAttribute(fused_attn_kernel,
                                 cudaFuncAttributeMaxDynamicSharedMemorySize, smem_bytes);
            smem_set = 1;
        }
        const dim3 grid(SEQ / 128, BATCH * NHEAD);
        fused_attn_kernel<<<grid, 256, smem_bytes>>>(attn);
    }

    // 3. output projection (fp32 out), 128x128 tiles
    {
        const dim3 grid(D_MODEL / 128, MROWS / 128, 1);
        out_proj_kernel<<<grid, 256>>>(b_o, outp);
    }
}

// round 11
// speedup vs baseline: 1.1720x; 1.0653x over previous
#include <cuda_runtime.h>
#include <cuda_fp16.h>
#include <math.h>
#include <stdint.h>

// Problem constants
#define D_MODEL 768
#define NHEAD   12
#define DK      64
#define BATCH   2
#define SEQ     2048
#define MROWS   (BATCH*SEQ)   // 4096
#define N1 (MROWS*D_MODEL)    // 3,145,728
#define N2 (D_MODEL*D_MODEL)  // 589,824

// Scratch in device globals (allocation-free rule)
__device__ __half g_xh[3 * N1];    // half copies of q,k,v inputs
__device__ __half g_wh[4 * N2];    // half copies of w_q,w_k,w_v,w_o
__device__ __half g_ph[3 * N1];    // projected qh, kh, vh (half)
__device__ __half g_ctxh[N1];      // attention context (half)
__device__ float  g_attn[(size_t)BATCH * NHEAD * SEQ * SEQ]; // fallback

// ---------------------------------------------------------------------------
// Low-level helpers
// ---------------------------------------------------------------------------
__device__ __forceinline__ uint32_t packh2(float x, float y) {
    __half2 h = __floats2half2_rn(x, y);
    return *reinterpret_cast<uint32_t*>(&h);
}

__device__ __forceinline__ void mma_f16(float* d, const uint32_t* a, const uint32_t* b) {
    asm volatile(
        "mma.sync.aligned.m16n8k16.row.col.f32.f16.f16.f32 "
        "{%0,%1,%2,%3}, {%4,%5,%6,%7}, {%8,%9}, {%0,%1,%2,%3};\n"
        : "+f"(d[0]), "+f"(d[1]), "+f"(d[2]), "+f"(d[3])
        : "r"(a[0]), "r"(a[1]), "r"(a[2]), "r"(a[3]), "r"(b[0]), "r"(b[1]));
}

__device__ __forceinline__ void ldsm_x4(uint32_t* r, const void* p) {
    uint32_t a = (uint32_t)__cvta_generic_to_shared(p);
    asm volatile("ldmatrix.sync.aligned.m8n8.x4.shared.b16 {%0,%1,%2,%3}, [%4];"
                 : "=r"(r[0]), "=r"(r[1]), "=r"(r[2]), "=r"(r[3]) : "r"(a));
}
__device__ __forceinline__ void ldsm_x4_t(uint32_t* r, const void* p) {
    uint32_t a = (uint32_t)__cvta_generic_to_shared(p);
    asm volatile("ldmatrix.sync.aligned.m8n8.x4.trans.shared.b16 {%0,%1,%2,%3}, [%4];"
                 : "=r"(r[0]), "=r"(r[1]), "=r"(r[2]), "=r"(r[3]) : "r"(a));
}

__device__ __forceinline__ void cp16(void* s, const void* g) {
    uint32_t a = (uint32_t)__cvta_generic_to_shared(s);
    asm volatile("cp.async.cg.shared.global [%0], [%1], 16;" :: "r"(a), "l"(g));
}
__device__ __forceinline__ void cp_commit() {
    asm volatile("cp.async.commit_group;" ::);
}
__device__ __forceinline__ void cp_wait1() {
    asm volatile("cp.async.wait_group 1;" ::);
}
__device__ __forceinline__ void cp_wait0() {
    asm volatile("cp.async.wait_group 0;" ::);
}

// ---------------------------------------------------------------------------
// Convert kernel: fp32 inputs/weights -> half scratch
// ---------------------------------------------------------------------------
__global__ void convert_kernel(const float* __restrict__ q, const float* __restrict__ k,
                               const float* __restrict__ v,
                               const float* __restrict__ wq, const float* __restrict__ wk,
                               const float* __restrict__ wv, const float* __restrict__ wo)
{
    const long long TOT4 = (3LL * N1 + 4LL * N2) / 4;
    for (long long i4 = blockIdx.x * blockDim.x + threadIdx.x; i4 < TOT4;
         i4 += (long long)gridDim.x * blockDim.x) {
        const long long e = i4 * 4;
        const float* src;
        __half* dst;
        if (e < 3LL * N1) {
            const int w = (int)(e / N1);
            const long long off = e - (long long)w * N1;
            src = (w == 0 ? q : w == 1 ? k : v) + off;
            dst = g_xh + e;
        } else {
            const long long e2 = e - 3LL * N1;
            const int w = (int)(e2 / N2);
            const long long off = e2 - (long long)w * N2;
            src = (w == 0 ? wq : w == 1 ? wk : w == 2 ? wv : wo) + off;
            dst = g_wh + e2;
        }
        const float4 f = *(const float4*)src;
        uint2 u;
        u.x = packh2(f.x, f.y);
        u.y = packh2(f.z, f.w);
        *(uint2*)dst = u;
    }
}

// ---------------------------------------------------------------------------
// 768-K GEMM body: C = A_h[4096x768] @ W_h[768x768] + bias
// Block tile 128x128, BK=32, cp.async double-buffer, ldmatrix fragments.
// 256 threads = 8 warps (4M x 2N), warp tile 32x64 (acc 64 regs).
// ---------------------------------------------------------------------------
template <bool HALF_OUT>
__device__ __forceinline__ void gemm768_body(const __half* __restrict__ A,
                                             const __half* __restrict__ W,
                                             const float* __restrict__ bias,
                                             void* __restrict__ C)
{
    __shared__ alignas(16) __half As[2][128][40];
    __shared__ alignas(16) __half Ws[2][32][136];

    const int tid  = threadIdx.x;
    const int warp = tid >> 5;
    const int lane = tid & 31;
    const int gid  = lane >> 2;
    const int tig  = lane & 3;
    const int wm   = (warp & 3) * 32;      // M: 4 groups of 32
    const int wn   = (warp >> 2) * 64;     // N: 2 groups of 64
    const int lrow = lane & 15;
    const int lcol = (lane >> 4) << 3;

    const int m0 = blockIdx.y * 128;
    const int n0 = blockIdx.x * 128;
    const __half* Ab = A + (long long)m0 * D_MODEL;
    const __half* Wb = W + n0;

    auto issueA = [&](int s, int k0) {
        #pragma unroll
        for (int it = 0; it < 2; it++) {
            const int c = tid + it * 256;        // 0..511
            const int row = c >> 2;              // 0..127
            const int ch  = (c & 3) * 8;         // 0..24
            cp16(&As[s][row][ch], Ab + (long long)row * D_MODEL + k0 + ch);
        }
    };
    auto issueW = [&](int s, int k0) {
        #pragma unroll
        for (int it = 0; it < 2; it++) {
            const int c = tid + it * 256;        // 0..511
            const int row = c >> 4;              // 0..31
            const int ch  = (c & 15) * 8;        // 0..120
            cp16(&Ws[s][row][ch], Wb + (long long)(k0 + row) * D_MODEL + ch);
        }
    };

    issueA(0, 0);
    issueW(0, 0);
    cp_commit();

    float acc[2][8][4] = {};

    for (int s = 0; s < 24; s++) {
        if (s < 23) {
            issueA((s + 1) & 1, (s + 1) * 32);
            issueW((s + 1) & 1, (s + 1) * 32);
            cp_commit();
            cp_wait1();
        } else {
            cp_wait0();
        }
        __syncthreads();

        const int bb = s & 1;
        #pragma unroll
        for (int kk = 0; kk < 32; kk += 16) {
            uint32_t af[2][4], bt[4][4];
            ldsm_x4(af[0], &As[bb][wm + lrow][kk + lcol]);
            ldsm_x4(af[1], &As[bb][wm + 16 + lrow][kk + lcol]);
            #pragma unroll
            for (int jj = 0; jj < 4; jj++)
                ldsm_x4_t(bt[jj], &Ws[bb][kk + lrow][wn + 16 * jj + lcol]);
            #pragma unroll
            for (int i = 0; i < 2; i++)
                #pragma unroll
                for (int jj = 0; jj < 4; jj++) {
                    mma_f16(acc[i][2 * jj],     af[i], &bt[jj][0]);
                    mma_f16(acc[i][2 * jj + 1], af[i], &bt[jj][2]);
                }
        }
        __syncthreads();
    }

    #pragma unroll
    for (int i = 0; i < 2; i++) {
        const int row = m0 + wm + 16 * i + gid;
        #pragma unroll
        for (int j = 0; j < 8; j++) {
            const int col = n0 + wn + 8 * j + 2 * tig;
            const float b0 = bias[col];
            const float b1 = bias[col + 1];
            const float v0 = acc[i][j][0] + b0;
            const float v1 = acc[i][j][1] + b1;
            const float v2 = acc[i][j][2] + b0;
            const float v3 = acc[i][j][3] + b1;
            if (HALF_OUT) {
                __half* Ch = (__half*)C;
                *(uint32_t*)(Ch + (long long)row * D_MODEL + col)       = packh2(v0, v1);
                *(uint32_t*)(Ch + (long long)(row + 8) * D_MODEL + col) = packh2(v2, v3);
            } else {
                float* Cf = (float*)C;
                *(float2*)(Cf + (long long)row * D_MODEL + col)       = make_float2(v0, v1);
                *(float2*)(Cf + (long long)(row + 8) * D_MODEL + col) = make_float2(v2, v3);
            }
        }
    }
}

__global__ __launch_bounds__(256, 2) void qkv_proj_kernel(
    const float* __restrict__ bq, const float* __restrict__ bk, const float* __restrict__ bv)
{
    const int z = blockIdx.z;
    const float* bias = (z == 0) ? bq : (z == 1) ? bk : bv;
    gemm768_body<true>(g_xh + (long long)z * N1, g_wh + (long long)z * N2,
                       bias, g_ph + (long long)z * N1);
}

__global__ __launch_bounds__(256, 2) void out_proj_kernel(
    const float* __restrict__ bo, float* __restrict__ out)
{
    gemm768_body<false>(g_ctxh, g_wh + 3LL * N2, bo, out);
}

// ---------------------------------------------------------------------------
// Fused attention: 256 threads, occ 2 (round-7 structure) with Q fragments
// hoisted to registers once (8 ldsm total instead of 8 per tile).
// Per (z, 128-q tile):
//   pass 1: S = Q K^T (fp16 MMA), rowsum of exp(S/8) — no gmem writes
//   pass 2: recompute S, p = exp(S/8)*inv, write p to attn (only touch),
//           stash half(p) in smem, ctx += p @ V
// ---------------------------------------------------------------------------
struct SmemAttn {
    __half Qs[128][72];      // 18 KB (used only to stage Q -> register frags)
    __half Ks[2][64][72];    // 18 KB double-buffered
    __half Vs[2][64][72];    // 18 KB double-buffered (pass 2 only)
    __half Ps[128][72];      // 18 KB normalized p (pass 2)
    float  rowsum[128];
};

__global__ __launch_bounds__(256, 2) void fused_attn_kernel(float* __restrict__ attn)
{
    extern __shared__ char smraw[];
    SmemAttn& sm = *reinterpret_cast<SmemAttn*>(smraw);

    const int tid  = threadIdx.x;
    const int warp = tid >> 5;
    const int lane = tid & 31;
    const int gid  = lane >> 2;
    const int tig  = lane & 3;
    const int wm   = (warp & 3) * 32;
    const int wn   = (warp >> 2) * 32;
    const int lrow = lane & 15;
    const int lcol = (lane >> 4) << 3;

    const int q0 = blockIdx.x * 128;
    const int z  = blockIdx.y;
    const int b  = z / NHEAD;
    const int h  = z % NHEAD;

    const __half* qb = g_ph + (long long)b * SEQ * D_MODEL + h * DK;
    const __half* kb = g_ph + N1 + (long long)b * SEQ * D_MODEL + h * DK;
    const __half* vb = g_ph + 2LL * N1 + (long long)b * SEQ * D_MODEL + h * DK;
    float* ab = attn + (long long)z * SEQ * SEQ;
    __half* cb = g_ctxh + (long long)b * SEQ * D_MODEL + h * DK;

    auto issueK = [&](int s, int n0) {
        #pragma unroll
        for (int it = 0; it < 2; it++) {
            const int c = tid + it * 256;
            const int key = c >> 3;
            const int ch  = (c & 7) * 8;
            cp16(&sm.Ks[s][key][ch], kb + (long long)(n0 + key) * D_MODEL + ch);
        }
    };
    auto issueV = [&](int s, int n0) {
        #pragma unroll
        for (int it = 0; it < 2; it++) {
            const int c = tid + it * 256;
            const int key = c >> 3;
            const int ch  = (c & 7) * 8;
            cp16(&sm.Vs[s][key][ch], vb + (long long)(n0 + key) * D_MODEL + ch);
        }
    };

    // prologue: Q tile + K tile 0
    #pragma unroll
    for (int it = 0; it < 4; it++) {
        const int c = tid + it * 256;
        const int row = c >> 3;
        const int ch  = (c & 7) * 8;
        cp16(&sm.Qs[row][ch], qb + (long long)(q0 + row) * D_MODEL + ch);
    }
    issueK(0, 0);
    cp_commit();
    if (tid < 128) sm.rowsum[tid] = 0.f;

    // Q fragments: loaded once at t==0 (after Q visible), live both passes.
    uint32_t qf[4][2][4];

    // =========================== PASS 1: rowsums ===========================
    for (int t = 0; t < 32; t++) {
        if (t < 31) {
            issueK((t + 1) & 1, (t + 1) * 64);
            cp_commit();
            cp_wait1();
        } else {
            cp_wait0();
        }
        __syncthreads();

        if (t == 0) {
            #pragma unroll
            for (int kk = 0; kk < 64; kk += 16) {
                ldsm_x4(qf[kk >> 4][0], &sm.Qs[wm + lrow][kk + lcol]);
                ldsm_x4(qf[kk >> 4][1], &sm.Qs[wm + 16 + lrow][kk + lcol]);
            }
        }

        const int bb = t & 1;
        float sacc[2][4][4] = {};
        #pragma unroll
        for (int kk = 0; kk < 64; kk += 16) {
            uint32_t kf[2][4];
            ldsm_x4(kf[0], &sm.Ks[bb][wn + lrow][kk + lcol]);
            ldsm_x4(kf[1], &sm.Ks[bb][wn + 16 + lrow][kk + lcol]);
            uint32_t b0[2] = { kf[0][0], kf[0][2] };
            uint32_t b1[2] = { kf[0][1], kf[0][3] };
            uint32_t b2[2] = { kf[1][0], kf[1][2] };
            uint32_t b3[2] = { kf[1][1], kf[1][3] };
            #pragma unroll
            for (int i = 0; i < 2; i++) {
                mma_f16(sacc[i][0], qf[kk >> 4][i], b0);
                mma_f16(sacc[i][1], qf[kk >> 4][i], b1);
                mma_f16(sacc[i][2], qf[kk >> 4][i], b2);
                mma_f16(sacc[i][3], qf[kk >> 4][i], b3);
            }
        }

        #pragma unroll
        for (int i = 0; i < 2; i++) {
            const int r = wm + 16 * i + gid;
            float s0 = 0.f, s1 = 0.f;
            #pragma unroll
            for (int j = 0; j < 4; j++) {
                s0 += __expf(sacc[i][j][0] * 0.125f) + __expf(sacc[i][j][1] * 0.125f);
                s1 += __expf(sacc[i][j][2] * 0.125f) + __expf(sacc[i][j][3] * 0.125f);
            }
            s0 += __shfl_xor_sync(0xffffffffu, s0, 1);
            s0 += __shfl_xor_sync(0xffffffffu, s0, 2);
            s1 += __shfl_xor_sync(0xffffffffu, s1, 1);
            s1 += __shfl_xor_sync(0xffffffffu, s1, 2);
            if (tig == 0) {
                atomicAdd(&sm.rowsum[r], s0);
                atomicAdd(&sm.rowsum[r + 8], s1);
            }
        }
        __syncthreads();
    }

    if (tid < 128) sm.rowsum[tid] = 1.0f / sm.rowsum[tid];
    __syncthreads();

    // hoist per-thread inverse rowsums
    float invr[2][2];
    #pragma unroll
    for (int i = 0; i < 2; i++) {
        invr[i][0] = sm.rowsum[wm + 16 * i + gid];
        invr[i][1] = sm.rowsum[wm + 16 * i + gid + 8];
    }

    // ================= PASS 2: recompute, write p, accumulate PV ===========
    issueK(0, 0);
    issueV(0, 0);
    cp_commit();

    float cacc[2][4][4] = {};

    for (int t = 0; t < 32; t++) {
        const int n0 = t * 64;
        if (t < 31) {
            issueK((t + 1) & 1, (t + 1) * 64);
            issueV((t + 1) & 1, (t + 1) * 64);
            cp_commit();
            cp_wait1();
        } else {
            cp_wait0();
        }
        __syncthreads();   // loads visible; prev iteration's PV done (Ps free)

        const int bb = t & 1;

        // scores recompute (Q from registers)
        float sacc[2][4][4] = {};
        #pragma unroll
        for (int kk = 0; kk < 64; kk += 16) {
            uint32_t kf[2][4];
            ldsm_x4(kf[0], &sm.Ks[bb][wn + lrow][kk + lcol]);
            ldsm_x4(kf[1], &sm.Ks[bb][wn + 16 + lrow][kk + lcol]);
            uint32_t b0[2] = { kf[0][0], kf[0][2] };
            uint32_t b1[2] = { kf[0][1], kf[0][3] };
            uint32_t b2[2] = { kf[1][0], kf[1][2] };
            uint32_t b3[2] = { kf[1][1], kf[1][3] };
            #pragma unroll
            for (int i = 0; i < 2; i++) {
                mma_f16(sacc[i][0], qf[kk >> 4][i], b0);
                mma_f16(sacc[i][1], qf[kk >> 4][i], b1);
                mma_f16(sacc[i][2], qf[kk >> 4][i], b2);
                mma_f16(sacc[i][3], qf[kk >> 4][i], b3);
            }
        }

        // normalized p: write to attn (only gmem touch) + stash half in Ps
        #pragma unroll
        for (int i = 0; i < 2; i++) {
            const int r = wm + 16 * i + gid;
            const float inv0 = invr[i][0];
            const float inv1 = invr[i][1];
            #pragma unroll
            for (int j = 0; j < 4; j++) {
                const int cl = wn + 8 * j + 2 * tig;
                float2 e01, e23;
                e01.x = __expf(sacc[i][j][0] * 0.125f) * inv0;
                e01.y = __expf(sacc[i][j][1] * 0.125f) * inv0;
                e23.x = __expf(sacc[i][j][2] * 0.125f) * inv1;
                e23.y = __expf(sacc[i][j][3] * 0.125f) * inv1;
                *(float2*)(ab + (long long)(q0 + r) * SEQ + n0 + cl)     = e01;
                *(float2*)(ab + (long long)(q0 + r + 8) * SEQ + n0 + cl) = e23;
                *(uint32_t*)&sm.Ps[r][cl]     = packh2(e01.x, e01.y);
                *(uint32_t*)&sm.Ps[r + 8][cl] = packh2(e23.x, e23.y);
            }
        }
        __syncthreads();   // Ps visible to all warps

        // PV MMA: ctx += P @ V
        #pragma unroll
        for (int kk = 0; kk < 64; kk += 16) {
            uint32_t af[2][4], vt[2][4];
            ldsm_x4(af[0], &sm.Ps[wm + lrow][kk + lcol]);
            ldsm_x4(af[1], &sm.Ps[wm + 16 + lrow][kk + lcol]);
            ldsm_x4_t(vt[0], &sm.Vs[bb][kk + lrow][wn + lcol]);
            ldsm_x4_t(vt[1], &sm.Vs[bb][kk + lrow][wn + 16 + lcol]);
            #pragma unroll
            for (int i = 0; i < 2; i++) {
                mma_f16(cacc[i][0], af[i], &vt[0][0]);
                mma_f16(cacc[i][1], af[i], &vt[0][2]);
                mma_f16(cacc[i][2], af[i], &vt[1][0]);
                mma_f16(cacc[i][3], af[i], &vt[1][2]);
            }
        }
        __syncthreads();   // Ks/Vs[bb] free for next iteration's prefetch
    }

    // ctx epilogue (half)
    #pragma unroll
    for (int i = 0; i < 2; i++) {
        const int row = q0 + wm + 16 * i + gid;
        #pragma unroll
        for (int j = 0; j < 4; j++) {
            const int col = wn + 8 * j + 2 * tig;
            *(uint32_t*)(cb + (long long)row * D_MODEL + col)       = packh2(cacc[i][j][0], cacc[i][j][1]);
            *(uint32_t*)(cb + (long long)(row + 8) * D_MODEL + col) = packh2(cacc[i][j][2], cacc[i][j][3]);
        }
    }
}

// ---------------------------------------------------------------------------
extern "C" void kernel_launch(void* const* d_in, const int* in_sizes, int n_in,
                              void* d_out, int out_size)
{
    const float* q   = (const float*)d_in[0];
    const float* k   = (const float*)d_in[1];
    const float* v   = (const float*)d_in[2];
    const float* w_q = (const float*)d_in[3];
    const float* b_q = (const float*)d_in[4];
    const float* w_k = (const float*)d_in[5];
    const float* b_k = (const float*)d_in[6];
    const float* w_v = (const float*)d_in[7];
    const float* b_v = (const float*)d_in[8];
    const float* w_o = (const float*)d_in[9];
    const float* b_o = (const float*)d_in[10];

    float* gattn;
    cudaGetSymbolAddress((void**)&gattn, g_attn);

    float* outp = (float*)d_out;
    const long long OUT_ELEMS  = (long long)MROWS * D_MODEL;
    const long long ATTN_ELEMS = (long long)BATCH * NHEAD * SEQ * SEQ;
    float* attn = ((long long)out_size >= OUT_ELEMS + ATTN_ELEMS) ? (outp + OUT_ELEMS)
                                                                  : gattn;

    // 0. convert inputs + weights to half
    convert_kernel<<<1024, 256>>>(q, k, v, w_q, w_k, w_v, w_o);

    // 1. QKV projections (half in, half out), 128x128 tiles
    {
        const dim3 grid(D_MODEL / 128, MROWS / 128, 3);
        qkv_proj_kernel<<<grid, 256>>>(b_q, b_k, b_v);
    }

    // 2. fused attention (scores + softmax + attn write + PV)
    {
        static int smem_set = 0;
        const int smem_bytes = (int)sizeof(SmemAttn);
        if (!smem_set) {
            cudaFuncSetAttribute(fused_attn_kernel,
                                 cudaFuncAttributeMaxDynamicSharedMemorySize, smem_bytes);
            smem_set = 1;
        }
        const dim3 grid(SEQ / 128, BATCH * NHEAD);
        fused_attn_kernel<<<grid, 256, smem_bytes>>>(attn);
    }

    // 3. output projection (fp32 out), 128x128 tiles
    {
        const dim3 grid(D_MODEL / 128, MROWS / 128, 1);
        out_proj_kernel<<<grid, 256>>>(b_o, outp);
    }
}

// round 12
// speedup vs baseline: 1.2224x; 1.0429x over previous
#include <cuda_runtime.h>
#include <cuda_fp16.h>
#include <math.h>
#include <stdint.h>

// Problem constants
#define D_MODEL 768
#define NHEAD   12
#define DK      64
#define BATCH   2
#define SEQ     2048
#define MROWS   (BATCH*SEQ)   // 4096
#define N1 (MROWS*D_MODEL)    // 3,145,728
#define N2 (D_MODEL*D_MODEL)  // 589,824

// Scratch in device globals (allocation-free rule)
__device__ __half g_xh[3 * N1];    // half copies of q,k,v inputs
__device__ __half g_wh[4 * N2];    // half copies of w_q,w_k,w_v,w_o
__device__ __half g_ph[3 * N1];    // projected qh, kh, vh (half)
__device__ __half g_ctxh[N1];      // attention context (half)
__device__ float  g_attn[(size_t)BATCH * NHEAD * SEQ * SEQ]; // fallback

// ---------------------------------------------------------------------------
// Low-level helpers
// ---------------------------------------------------------------------------
__device__ __forceinline__ uint32_t packh2(float x, float y) {
    __half2 h = __floats2half2_rn(x, y);
    return *reinterpret_cast<uint32_t*>(&h);
}

__device__ __forceinline__ void mma_f16(float* d, const uint32_t* a, const uint32_t* b) {
    asm volatile(
        "mma.sync.aligned.m16n8k16.row.col.f32.f16.f16.f32 "
        "{%0,%1,%2,%3}, {%4,%5,%6,%7}, {%8,%9}, {%0,%1,%2,%3};\n"
        : "+f"(d[0]), "+f"(d[1]), "+f"(d[2]), "+f"(d[3])
        : "r"(a[0]), "r"(a[1]), "r"(a[2]), "r"(a[3]), "r"(b[0]), "r"(b[1]));
}

__device__ __forceinline__ void ldsm_x4(uint32_t* r, const void* p) {
    uint32_t a = (uint32_t)__cvta_generic_to_shared(p);
    asm volatile("ldmatrix.sync.aligned.m8n8.x4.shared.b16 {%0,%1,%2,%3}, [%4];"
                 : "=r"(r[0]), "=r"(r[1]), "=r"(r[2]), "=r"(r[3]) : "r"(a));
}
__device__ __forceinline__ void ldsm_x4_t(uint32_t* r, const void* p) {
    uint32_t a = (uint32_t)__cvta_generic_to_shared(p);
    asm volatile("ldmatrix.sync.aligned.m8n8.x4.trans.shared.b16 {%0,%1,%2,%3}, [%4];"
                 : "=r"(r[0]), "=r"(r[1]), "=r"(r[2]), "=r"(r[3]) : "r"(a));
}

__device__ __forceinline__ void cp16(void* s, const void* g) {
    uint32_t a = (uint32_t)__cvta_generic_to_shared(s);
    asm volatile("cp.async.cg.shared.global [%0], [%1], 16;" :: "r"(a), "l"(g));
}
__device__ __forceinline__ void cp_commit() {
    asm volatile("cp.async.commit_group;" ::);
}
__device__ __forceinline__ void cp_wait1() {
    asm volatile("cp.async.wait_group 1;" ::);
}
__device__ __forceinline__ void cp_wait0() {
    asm volatile("cp.async.wait_group 0;" ::);
}

// ---------------------------------------------------------------------------
// Convert kernel: fp32 inputs/weights -> half scratch
// ---------------------------------------------------------------------------
__global__ void convert_kernel(const float* __restrict__ q, const float* __restrict__ k,
                               const float* __restrict__ v,
                               const float* __restrict__ wq, const float* __restrict__ wk,
                               const float* __restrict__ wv, const float* __restrict__ wo)
{
    const long long TOT4 = (3LL * N1 + 4LL * N2) / 4;
    for (long long i4 = blockIdx.x * blockDim.x + threadIdx.x; i4 < TOT4;
         i4 += (long long)gridDim.x * blockDim.x) {
        const long long e = i4 * 4;
        const float* src;
        __half* dst;
        if (e < 3LL * N1) {
            const int w = (int)(e / N1);
            const long long off = e - (long long)w * N1;
            src = (w == 0 ? q : w == 1 ? k : v) + off;
            dst = g_xh + e;
        } else {
            const long long e2 = e - 3LL * N1;
            const int w = (int)(e2 / N2);
            const long long off = e2 - (long long)w * N2;
            src = (w == 0 ? wq : w == 1 ? wk : w == 2 ? wv : wo) + off;
            dst = g_wh + e2;
        }
        const float4 f = *(const float4*)src;
        uint2 u;
        u.x = packh2(f.x, f.y);
        u.y = packh2(f.z, f.w);
        *(uint2*)dst = u;
    }
}

// ---------------------------------------------------------------------------
// 768-K GEMM body: C = A_h[4096x768] @ W_h[768x768] + bias
// Block tile 128x128, BK=32, cp.async double-buffer, ldmatrix fragments.
// 256 threads = 8 warps (4M x 2N), warp tile 32x64 (acc 64 regs).
// ---------------------------------------------------------------------------
template <bool HALF_OUT>
__device__ __forceinline__ void gemm768_body(const __half* __restrict__ A,
                                             const __half* __restrict__ W,
                                             const float* __restrict__ bias,
                                             void* __restrict__ C)
{
    __shared__ alignas(16) __half As[2][128][40];
    __shared__ alignas(16) __half Ws[2][32][136];

    const int tid  = threadIdx.x;
    const int warp = tid >> 5;
    const int lane = tid & 31;
    const int gid  = lane >> 2;
    const int tig  = lane & 3;
    const int wm   = (warp & 3) * 32;      // M: 4 groups of 32
    const int wn   = (warp >> 2) * 64;     // N: 2 groups of 64
    const int lrow = lane & 15;
    const int lcol = (lane >> 4) << 3;

    const int m0 = blockIdx.y * 128;
    const int n0 = blockIdx.x * 128;
    const __half* Ab = A + (long long)m0 * D_MODEL;
    const __half* Wb = W + n0;

    auto issueA = [&](int s, int k0) {
        #pragma unroll
        for (int it = 0; it < 2; it++) {
            const int c = tid + it * 256;        // 0..511
            const int row = c >> 2;              // 0..127
            const int ch  = (c & 3) * 8;         // 0..24
            cp16(&As[s][row][ch], Ab + (long long)row * D_MODEL + k0 + ch);
        }
    };
    auto issueW = [&](int s, int k0) {
        #pragma unroll
        for (int it = 0; it < 2; it++) {
            const int c = tid + it * 256;        // 0..511
            const int row = c >> 4;              // 0..31
            const int ch  = (c & 15) * 8;        // 0..120
            cp16(&Ws[s][row][ch], Wb + (long long)(k0 + row) * D_MODEL + ch);
        }
    };

    issueA(0, 0);
    issueW(0, 0);
    cp_commit();

    float acc[2][8][4] = {};

    for (int s = 0; s < 24; s++) {
        if (s < 23) {
            issueA((s + 1) & 1, (s + 1) * 32);
            issueW((s + 1) & 1, (s + 1) * 32);
            cp_commit();
            cp_wait1();
        } else {
            cp_wait0();
        }
        __syncthreads();

        const int bb = s & 1;
        #pragma unroll
        for (int kk = 0; kk < 32; kk += 16) {
            uint32_t af[2][4], bt[4][4];
            ldsm_x4(af[0], &As[bb][wm + lrow][kk + lcol]);
            ldsm_x4(af[1], &As[bb][wm + 16 + lrow][kk + lcol]);
            #pragma unroll
            for (int jj = 0; jj < 4; jj++)
                ldsm_x4_t(bt[jj], &Ws[bb][kk + lrow][wn + 16 * jj + lcol]);
            #pragma unroll
            for (int i = 0; i < 2; i++)
                #pragma unroll
                for (int jj = 0; jj < 4; jj++) {
                    mma_f16(acc[i][2 * jj],     af[i], &bt[jj][0]);
                    mma_f16(acc[i][2 * jj + 1], af[i], &bt[jj][2]);
                }
        }
        __syncthreads();
    }

    #pragma unroll
    for (int i = 0; i < 2; i++) {
        const int row = m0 + wm + 16 * i + gid;
        #pragma unroll
        for (int j = 0; j < 8; j++) {
            const int col = n0 + wn + 8 * j + 2 * tig;
            const float b0 = bias[col];
            const float b1 = bias[col + 1];
            const float v0 = acc[i][j][0] + b0;
            const float v1 = acc[i][j][1] + b1;
            const float v2 = acc[i][j][2] + b0;
            const float v3 = acc[i][j][3] + b1;
            if (HALF_OUT) {
                __half* Ch = (__half*)C;
                *(uint32_t*)(Ch + (long long)row * D_MODEL + col)       = packh2(v0, v1);
                *(uint32_t*)(Ch + (long long)(row + 8) * D_MODEL + col) = packh2(v2, v3);
            } else {
                float* Cf = (float*)C;
                *(float2*)(Cf + (long long)row * D_MODEL + col)       = make_float2(v0, v1);
                *(float2*)(Cf + (long long)(row + 8) * D_MODEL + col) = make_float2(v2, v3);
            }
        }
    }
}

__global__ __launch_bounds__(256, 2) void qkv_proj_kernel(
    const float* __restrict__ bq, const float* __restrict__ bk, const float* __restrict__ bv)
{
    const int z = blockIdx.z;
    const float* bias = (z == 0) ? bq : (z == 1) ? bk : bv;
    gemm768_body<true>(g_xh + (long long)z * N1, g_wh + (long long)z * N2,
                       bias, g_ph + (long long)z * N1);
}

__global__ __launch_bounds__(256, 2) void out_proj_kernel(
    const float* __restrict__ bo, float* __restrict__ out)
{
    gemm768_body<false>(g_ctxh, g_wh + 3LL * N2, bo, out);
}

// ---------------------------------------------------------------------------
// Fused attention, FA2-style warp layout: 8 warps x m16 slabs; each warp owns
// 16 q-rows and the full 64-key / 64-dk width. P never leaves registers:
// the m16n8 score accumulator IS the A-fragment of the PV m16n8k16 MMA.
//   pass 1: S = Q K^T, per-warp register rowsums of exp(S/8) (no atomics)
//   pass 2: recompute S, p = exp(S/8)*inv, write p to attn (only gmem touch),
//           ctx += p @ V straight from registers
// ---------------------------------------------------------------------------
struct SmemAttn {
    __half Qs[128][72];      // 18 KB (stages Q -> register frags)
    __half Ks[2][64][72];    // 18 KB double-buffered
    __half Vs[2][64][72];    // 18 KB double-buffered (pass 2 only)
};

__global__ __launch_bounds__(256, 2) void fused_attn_kernel(float* __restrict__ attn)
{
    extern __shared__ char smraw[];
    SmemAttn& sm = *reinterpret_cast<SmemAttn*>(smraw);

    const int tid  = threadIdx.x;
    const int warp = tid >> 5;            // 0..7
    const int lane = tid & 31;
    const int gid  = lane >> 2;
    const int tig  = lane & 3;
    const int wm   = warp * 16;           // warp's 16 q-rows
    const int lrow = lane & 15;
    const int lcol = (lane >> 4) << 3;

    const int q0 = blockIdx.x * 128;
    const int z  = blockIdx.y;
    const int b  = z / NHEAD;
    const int h  = z % NHEAD;

    const __half* qb = g_ph + (long long)b * SEQ * D_MODEL + h * DK;
    const __half* kb = g_ph + N1 + (long long)b * SEQ * D_MODEL + h * DK;
    const __half* vb = g_ph + 2LL * N1 + (long long)b * SEQ * D_MODEL + h * DK;
    float* ab = attn + (long long)z * SEQ * SEQ;
    __half* cb = g_ctxh + (long long)b * SEQ * D_MODEL + h * DK;

    auto issueK = [&](int s, int n0) {
        #pragma unroll
        for (int it = 0; it < 2; it++) {
            const int c = tid + it * 256;
            const int key = c >> 3;
            const int ch  = (c & 7) * 8;
            cp16(&sm.Ks[s][key][ch], kb + (long long)(n0 + key) * D_MODEL + ch);
        }
    };
    auto issueV = [&](int s, int n0) {
        #pragma unroll
        for (int it = 0; it < 2; it++) {
            const int c = tid + it * 256;
            const int key = c >> 3;
            const int ch  = (c & 7) * 8;
            cp16(&sm.Vs[s][key][ch], vb + (long long)(n0 + key) * D_MODEL + ch);
        }
    };

    // prologue: Q tile + K tile 0
    #pragma unroll
    for (int it = 0; it < 4; it++) {
        const int c = tid + it * 256;
        const int row = c >> 3;
        const int ch  = (c & 7) * 8;
        cp16(&sm.Qs[row][ch], qb + (long long)(q0 + row) * D_MODEL + ch);
    }
    issueK(0, 0);
    cp_commit();

    // Q fragments (m16 x k64): 4 ldsm_x4, live through both passes.
    uint32_t qf[4][4];

    // =========================== PASS 1: rowsums ===========================
    float rs0 = 0.f, rs1 = 0.f;   // rows wm+gid, wm+gid+8 (warp-exclusive)

    for (int t = 0; t < 32; t++) {
        if (t < 31) {
            issueK((t + 1) & 1, (t + 1) * 64);
            cp_commit();
            cp_wait1();
        } else {
            cp_wait0();
        }
        __syncthreads();

        if (t == 0) {
            #pragma unroll
            for (int kk = 0; kk < 4; kk++)
                ldsm_x4(qf[kk], &sm.Qs[wm + lrow][16 * kk + lcol]);
        }

        const int bb = t & 1;
        float sacc[8][4] = {};
        #pragma unroll
        for (int kk = 0; kk < 4; kk++) {
            uint32_t kf[4][4];
            #pragma unroll
            for (int nb = 0; nb < 4; nb++)
                ldsm_x4(kf[nb], &sm.Ks[bb][16 * nb + lrow][16 * kk + lcol]);
            #pragma unroll
            for (int nb = 0; nb < 4; nb++) {
                uint32_t b0[2] = { kf[nb][0], kf[nb][2] };
                uint32_t b1[2] = { kf[nb][1], kf[nb][3] };
                mma_f16(sacc[2 * nb],     qf[kk], b0);
                mma_f16(sacc[2 * nb + 1], qf[kk], b1);
            }
        }

        #pragma unroll
        for (int jn = 0; jn < 8; jn++) {
            rs0 += __expf(sacc[jn][0] * 0.125f) + __expf(sacc[jn][1] * 0.125f);
            rs1 += __expf(sacc[jn][2] * 0.125f) + __expf(sacc[jn][3] * 0.125f);
        }
        __syncthreads();
    }

    // warp-local reduce over the 4 tig lanes holding the same row
    rs0 += __shfl_xor_sync(0xffffffffu, rs0, 1);
    rs0 += __shfl_xor_sync(0xffffffffu, rs0, 2);
    rs1 += __shfl_xor_sync(0xffffffffu, rs1, 1);
    rs1 += __shfl_xor_sync(0xffffffffu, rs1, 2);
    const float inv0 = 1.0f / rs0;
    const float inv1 = 1.0f / rs1;

    // ================= PASS 2: recompute, write p, accumulate PV ===========
    issueK(0, 0);
    issueV(0, 0);
    cp_commit();

    float cacc[8][4] = {};

    for (int t = 0; t < 32; t++) {
        const int n0 = t * 64;
        if (t < 31) {
            issueK((t + 1) & 1, (t + 1) * 64);
            issueV((t + 1) & 1, (t + 1) * 64);
            cp_commit();
            cp_wait1();
        } else {
            cp_wait0();
        }
        __syncthreads();

        const int bb = t & 1;

        // scores recompute (Q from registers)
        float sacc[8][4] = {};
        #pragma unroll
        for (int kk = 0; kk < 4; kk++) {
            uint32_t kf[4][4];
            #pragma unroll
            for (int nb = 0; nb < 4; nb++)
                ldsm_x4(kf[nb], &sm.Ks[bb][16 * nb + lrow][16 * kk + lcol]);
            #pragma unroll
            for (int nb = 0; nb < 4; nb++) {
                uint32_t b0[2] = { kf[nb][0], kf[nb][2] };
                uint32_t b1[2] = { kf[nb][1], kf[nb][3] };
                mma_f16(sacc[2 * nb],     qf[kk], b0);
                mma_f16(sacc[2 * nb + 1], qf[kk], b1);
            }
        }

        // normalize + write attn + pack P as A-fragments (registers only)
        uint32_t pa[8][2];
        {
            const int r0 = q0 + wm + gid;
            #pragma unroll
            for (int jn = 0; jn < 8; jn++) {
                const int cl = n0 + 8 * jn + 2 * tig;
                float2 e01, e23;
                e01.x = __expf(sacc[jn][0] * 0.125f) * inv0;
                e01.y = __expf(sacc[jn][1] * 0.125f) * inv0;
                e23.x = __expf(sacc[jn][2] * 0.125f) * inv1;
                e23.y = __expf(sacc[jn][3] * 0.125f) * inv1;
                *(float2*)(ab + (long long)r0 * SEQ + cl)       = e01;
                *(float2*)(ab + (long long)(r0 + 8) * SEQ + cl) = e23;
                pa[jn][0] = packh2(e01.x, e01.y);
                pa[jn][1] = packh2(e23.x, e23.y);
            }
        }

        // PV MMA: ctx += P @ V, P straight from registers
        #pragma unroll
        for (int c = 0; c < 4; c++) {
            uint32_t A[4] = { pa[2 * c][0], pa[2 * c][1],
                              pa[2 * c + 1][0], pa[2 * c + 1][1] };
            uint32_t vt[4][4];
            #pragma unroll
            for (int nb = 0; nb < 4; nb++)
                ldsm_x4_t(vt[nb], &sm.Vs[bb][16 * c + lrow][16 * nb + lcol]);
            #pragma unroll
            for (int nb = 0; nb < 4; nb++) {
                mma_f16(cacc[2 * nb],     A, &vt[nb][0]);
                mma_f16(cacc[2 * nb + 1], A, &vt[nb][2]);
            }
        }
        __syncthreads();   // Ks/Vs[bb] free for next iteration's prefetch
    }

    // ctx epilogue (half)
    {
        const int row = q0 + wm + gid;
        #pragma unroll
        for (int jn = 0; jn < 8; jn++) {
            const int col = 8 * jn + 2 * tig;
            *(uint32_t*)(cb + (long long)row * D_MODEL + col)       = packh2(cacc[jn][0], cacc[jn][1]);
            *(uint32_t*)(cb + (long long)(row + 8) * D_MODEL + col) = packh2(cacc[jn][2], cacc[jn][3]);
        }
    }
}

// ---------------------------------------------------------------------------
extern "C" void kernel_launch(void* const* d_in, const int* in_sizes, int n_in,
                              void* d_out, int out_size)
{
    const float* q   = (const float*)d_in[0];
    const float* k   = (const float*)d_in[1];
    const float* v   = (const float*)d_in[2];
    const float* w_q = (const float*)d_in[3];
    const float* b_q = (const float*)d_in[4];
    const float* w_k = (const float*)d_in[5];
    const float* b_k = (const float*)d_in[6];
    const float* w_v = (const float*)d_in[7];
    const float* b_v = (const float*)d_in[8];
    const float* w_o = (const float*)d_in[9];
    const float* b_o = (const float*)d_in[10];

    float* gattn;
    cudaGetSymbolAddress((void**)&gattn, g_attn);

    float* outp = (float*)d_out;
    const long long OUT_ELEMS  = (long long)MROWS * D_MODEL;
    const long long ATTN_ELEMS = (long long)BATCH * NHEAD * SEQ * SEQ;
    float* attn = ((long long)out_size >= OUT_ELEMS + ATTN_ELEMS) ? (outp + OUT_ELEMS)
                                                                  : gattn;

    // 0. convert inputs + weights to half
    convert_kernel<<<1024, 256>>>(q, k, v, w_q, w_k, w_v, w_o);

    // 1. QKV projections (half in, half out), 128x128 tiles
    {
        const dim3 grid(D_MODEL / 128, MROWS / 128, 3);
        qkv_proj_kernel<<<grid, 256>>>(b_q, b_k, b_v);
    }

    // 2. fused attention (scores + softmax + attn write + PV)
    {
        static int smem_set = 0;
        const int smem_bytes = (int)sizeof(SmemAttn);
        if (!smem_set) {
            cudaFuncSetAttribute(fused_attn_kernel,
                                 cudaFuncAttributeMaxDynamicSharedMemorySize, smem_bytes);
            smem_set = 1;
        }
        const dim3 grid(SEQ / 128, BATCH * NHEAD);
        fused_attn_kernel<<<grid, 256, smem_bytes>>>(attn);
    }

    // 3. output projection (fp32 out), 128x128 tiles
    {
        const dim3 grid(D_MODEL / 128, MROWS / 128, 1);
        out_proj_kernel<<<grid, 256>>>(b_o, outp);
    }
}

// round 14
// speedup vs baseline: 1.2304x; 1.0066x over previous
#include <cuda_runtime.h>
#include <cuda_fp16.h>
#include <math.h>
#include <stdint.h>

// Problem constants
#define D_MODEL 768
#define NHEAD   12
#define DK      64
#define BATCH   2
#define SEQ     2048
#define MROWS   (BATCH*SEQ)   // 4096
#define N1 (MROWS*D_MODEL)    // 3,145,728
#define N2 (D_MODEL*D_MODEL)  // 589,824

// Scratch in device globals (allocation-free rule)
__device__ __half g_xh[3 * N1];    // half copies of q,k,v inputs
__device__ __half g_wh[4 * N2];    // half copies of w_q,w_k,w_v,w_o
__device__ __half g_ph[3 * N1];    // projected qh, kh, vh (half)
__device__ __half g_ctxh[N1];      // attention context (half)
__device__ float  g_inv[BATCH * NHEAD * SEQ];
__device__ float  g_attn[(size_t)BATCH * NHEAD * SEQ * SEQ]; // fallback

// ---------------------------------------------------------------------------
// Low-level helpers
// ---------------------------------------------------------------------------
__device__ __forceinline__ uint32_t packh2(float x, float y) {
    __half2 h = __floats2half2_rn(x, y);
    return *reinterpret_cast<uint32_t*>(&h);
}

__device__ __forceinline__ void mma_f16(float* d, const uint32_t* a, const uint32_t* b) {
    asm volatile(
        "mma.sync.aligned.m16n8k16.row.col.f32.f16.f16.f32 "
        "{%0,%1,%2,%3}, {%4,%5,%6,%7}, {%8,%9}, {%0,%1,%2,%3};\n"
        : "+f"(d[0]), "+f"(d[1]), "+f"(d[2]), "+f"(d[3])
        : "r"(a[0]), "r"(a[1]), "r"(a[2]), "r"(a[3]), "r"(b[0]), "r"(b[1]));
}

__device__ __forceinline__ void ldsm_x4(uint32_t* r, const void* p) {
    uint32_t a = (uint32_t)__cvta_generic_to_shared(p);
    asm volatile("ldmatrix.sync.aligned.m8n8.x4.shared.b16 {%0,%1,%2,%3}, [%4];"
                 : "=r"(r[0]), "=r"(r[1]), "=r"(r[2]), "=r"(r[3]) : "r"(a));
}
__device__ __forceinline__ void ldsm_x4_t(uint32_t* r, const void* p) {
    uint32_t a = (uint32_t)__cvta_generic_to_shared(p);
    asm volatile("ldmatrix.sync.aligned.m8n8.x4.trans.shared.b16 {%0,%1,%2,%3}, [%4];"
                 : "=r"(r[0]), "=r"(r[1]), "=r"(r[2]), "=r"(r[3]) : "r"(a));
}

__device__ __forceinline__ void cp16(void* s, const void* g) {
    uint32_t a = (uint32_t)__cvta_generic_to_shared(s);
    asm volatile("cp.async.cg.shared.global [%0], [%1], 16;" :: "r"(a), "l"(g));
}
__device__ __forceinline__ void cp_commit() {
    asm volatile("cp.async.commit_group;" ::);
}
__device__ __forceinline__ void cp_wait1() {
    asm volatile("cp.async.wait_group 1;" ::);
}
__device__ __forceinline__ void cp_wait0() {
    asm volatile("cp.async.wait_group 0;" ::);
}

__device__ __forceinline__ void stg_cs_f2(float* p, float x, float y) {
    asm volatile("st.global.cs.v2.f32 [%0], {%1,%2};" :: "l"(p), "f"(x), "f"(y) : "memory");
}

// ---------------------------------------------------------------------------
// Convert kernel: fp32 inputs/weights -> half scratch
// ---------------------------------------------------------------------------
__global__ void convert_kernel(const float* __restrict__ q, const float* __restrict__ k,
                               const float* __restrict__ v,
                               const float* __restrict__ wq, const float* __restrict__ wk,
                               const float* __restrict__ wv, const float* __restrict__ wo)
{
    const long long TOT4 = (3LL * N1 + 4LL * N2) / 4;
    for (long long i4 = blockIdx.x * blockDim.x + threadIdx.x; i4 < TOT4;
         i4 += (long long)gridDim.x * blockDim.x) {
        const long long e = i4 * 4;
        const float* src;
        __half* dst;
        if (e < 3LL * N1) {
            const int w = (int)(e / N1);
            const long long off = e - (long long)w * N1;
            src = (w == 0 ? q : w == 1 ? k : v) + off;
            dst = g_xh + e;
        } else {
            const long long e2 = e - 3LL * N1;
            const int w = (int)(e2 / N2);
            const long long off = e2 - (long long)w * N2;
            src = (w == 0 ? wq : w == 1 ? wk : w == 2 ? wv : wo) + off;
            dst = g_wh + e2;
        }
        const float4 f = *(const float4*)src;
        uint2 u;
        u.x = packh2(f.x, f.y);
        u.y = packh2(f.z, f.w);
        *(uint2*)dst = u;
    }
}

// ---------------------------------------------------------------------------
// 768-K GEMM body: C = A_h[4096x768] @ W_h[768x768] + bias
// Block tile 128x128, BK=32, cp.async double-buffer, ldmatrix fragments.
// 256 threads = 8 warps (4M x 2N), warp tile 32x64 (acc 64 regs).
// ---------------------------------------------------------------------------
template <bool HALF_OUT>
__device__ __forceinline__ void gemm768_body(const __half* __restrict__ A,
                                             const __half* __restrict__ W,
                                             const float* __restrict__ bias,
                                             void* __restrict__ C)
{
    __shared__ alignas(16) __half As[2][128][40];
    __shared__ alignas(16) __half Ws[2][32][136];

    const int tid  = threadIdx.x;
    const int warp = tid >> 5;
    const int lane = tid & 31;
    const int gid  = lane >> 2;
    const int tig  = lane & 3;
    const int wm   = (warp & 3) * 32;      // M: 4 groups of 32
    const int wn   = (warp >> 2) * 64;     // N: 2 groups of 64
    const int lrow = lane & 15;
    const int lcol = (lane >> 4) << 3;

    const int m0 = blockIdx.y * 128;
    const int n0 = blockIdx.x * 128;
    const __half* Ab = A + (long long)m0 * D_MODEL;
    const __half* Wb = W + n0;

    auto issueA = [&](int s, int k0) {
        #pragma unroll
        for (int it = 0; it < 2; it++) {
            const int c = tid + it * 256;        // 0..511
            const int row = c >> 2;              // 0..127
            const int ch  = (c & 3) * 8;         // 0..24
            cp16(&As[s][row][ch], Ab + (long long)row * D_MODEL + k0 + ch);
        }
    };
    auto issueW = [&](int s, int k0) {
        #pragma unroll
        for (int it = 0; it < 2; it++) {
            const int c = tid + it * 256;        // 0..511
            const int row = c >> 4;              // 0..31
            const int ch  = (c & 15) * 8;        // 0..120
            cp16(&Ws[s][row][ch], Wb + (long long)(k0 + row) * D_MODEL + ch);
        }
    };

    issueA(0, 0);
    issueW(0, 0);
    cp_commit();

    float acc[2][8][4] = {};

    for (int s = 0; s < 24; s++) {
        if (s < 23) {
            issueA((s + 1) & 1, (s + 1) * 32);
            issueW((s + 1) & 1, (s + 1) * 32);
            cp_commit();
            cp_wait1();
        } else {
            cp_wait0();
        }
        __syncthreads();

        const int bb = s & 1;
        #pragma unroll
        for (int kk = 0; kk < 32; kk += 16) {
            uint32_t af[2][4], bt[4][4];
            ldsm_x4(af[0], &As[bb][wm + lrow][kk + lcol]);
            ldsm_x4(af[1], &As[bb][wm + 16 + lrow][kk + lcol]);
            #pragma unroll
            for (int jj = 0; jj < 4; jj++)
                ldsm_x4_t(bt[jj], &Ws[bb][kk + lrow][wn + 16 * jj + lcol]);
            #pragma unroll
            for (int i = 0; i < 2; i++)
                #pragma unroll
                for (int jj = 0; jj < 4; jj++) {
                    mma_f16(acc[i][2 * jj],     af[i], &bt[jj][0]);
                    mma_f16(acc[i][2 * jj + 1], af[i], &bt[jj][2]);
                }
        }
        __syncthreads();
    }

    #pragma unroll
    for (int i = 0; i < 2; i++) {
        const int row = m0 + wm + 16 * i + gid;
        #pragma unroll
        for (int j = 0; j < 8; j++) {
            const int col = n0 + wn + 8 * j + 2 * tig;
            const float b0 = bias[col];
            const float b1 = bias[col + 1];
            const float v0 = acc[i][j][0] + b0;
            const float v1 = acc[i][j][1] + b1;
            const float v2 = acc[i][j][2] + b0;
            const float v3 = acc[i][j][3] + b1;
            if (HALF_OUT) {
                __half* Ch = (__half*)C;
                *(uint32_t*)(Ch + (long long)row * D_MODEL + col)       = packh2(v0, v1);
                *(uint32_t*)(Ch + (long long)(row + 8) * D_MODEL + col) = packh2(v2, v3);
            } else {
                float* Cf = (float*)C;
                *(float2*)(Cf + (long long)row * D_MODEL + col)       = make_float2(v0, v1);
                *(float2*)(Cf + (long long)(row + 8) * D_MODEL + col) = make_float2(v2, v3);
            }
        }
    }
}

__global__ __launch_bounds__(256, 2) void qkv_proj_kernel(
    const float* __restrict__ bq, const float* __restrict__ bk, const float* __restrict__ bv)
{
    const int z = blockIdx.z;
    const float* bias = (z == 0) ? bq : (z == 1) ? bk : bv;
    gemm768_body<true>(g_xh + (long long)z * N1, g_wh + (long long)z * N2,
                       bias, g_ph + (long long)z * N1);
}

__global__ __launch_bounds__(256, 2) void out_proj_kernel(
    const float* __restrict__ bo, float* __restrict__ out)
{
    gemm768_body<false>(g_ctxh, g_wh + 3LL * N2, bo, out);
}

// ---------------------------------------------------------------------------
// Attention pass 1 (separate kernel for occupancy 3): per (z, 128-q tile)
// rowsums of exp(S/8) -> g_inv. 8 warps x m16 slabs; no gmem writes but g_inv.
// Registers: sacc 32 + qf 16 + misc -> fits 85-reg budget at occ 3.
// ---------------------------------------------------------------------------
struct SmemP1 {
    __half Qs[128][72];      // 18 KB
    __half Ks[2][64][72];    // 18 KB double-buffered
};

__global__ __launch_bounds__(256, 3) void attn_pass1_kernel()
{
    extern __shared__ char smraw[];
    SmemP1& sm = *reinterpret_cast<SmemP1*>(smraw);

    const int tid  = threadIdx.x;
    const int warp = tid >> 5;
    const int lane = tid & 31;
    const int gid  = lane >> 2;
    const int tig  = lane & 3;
    const int wm   = warp * 16;
    const int lrow = lane & 15;
    const int lcol = (lane >> 4) << 3;

    const int q0 = blockIdx.x * 128;
    const int z  = blockIdx.y;
    const int b  = z / NHEAD;
    const int h  = z % NHEAD;

    const __half* qb = g_ph + (long long)b * SEQ * D_MODEL + h * DK;
    const __half* kb = g_ph + N1 + (long long)b * SEQ * D_MODEL + h * DK;

    auto issueK = [&](int s, int n0) {
        #pragma unroll
        for (int it = 0; it < 2; it++) {
            const int c = tid + it * 256;
            const int key = c >> 3;
            const int ch  = (c & 7) * 8;
            cp16(&sm.Ks[s][key][ch], kb + (long long)(n0 + key) * D_MODEL + ch);
        }
    };

    #pragma unroll
    for (int it = 0; it < 4; it++) {
        const int c = tid + it * 256;
        const int row = c >> 3;
        const int ch  = (c & 7) * 8;
        cp16(&sm.Qs[row][ch], qb + (long long)(q0 + row) * D_MODEL + ch);
    }
    issueK(0, 0);
    cp_commit();

    uint32_t qf[4][4];
    float rs0 = 0.f, rs1 = 0.f;

    for (int t = 0; t < 32; t++) {
        if (t < 31) {
            issueK((t + 1) & 1, (t + 1) * 64);
            cp_commit();
            cp_wait1();
        } else {
            cp_wait0();
        }
        __syncthreads();

        if (t == 0) {
            #pragma unroll
            for (int kk = 0; kk < 4; kk++)
                ldsm_x4(qf[kk], &sm.Qs[wm + lrow][16 * kk + lcol]);
        }

        const int bb = t & 1;
        float sacc[8][4] = {};
        #pragma unroll
        for (int kk = 0; kk < 4; kk++) {
            uint32_t kf[4][4];
            #pragma unroll
            for (int nb = 0; nb < 4; nb++)
                ldsm_x4(kf[nb], &sm.Ks[bb][16 * nb + lrow][16 * kk + lcol]);
            #pragma unroll
            for (int nb = 0; nb < 4; nb++) {
                uint32_t b0[2] = { kf[nb][0], kf[nb][2] };
                uint32_t b1[2] = { kf[nb][1], kf[nb][3] };
                mma_f16(sacc[2 * nb],     qf[kk], b0);
                mma_f16(sacc[2 * nb + 1], qf[kk], b1);
            }
        }

        #pragma unroll
        for (int jn = 0; jn < 8; jn++) {
            rs0 += __expf(sacc[jn][0] * 0.125f) + __expf(sacc[jn][1] * 0.125f);
            rs1 += __expf(sacc[jn][2] * 0.125f) + __expf(sacc[jn][3] * 0.125f);
        }
        __syncthreads();
    }

    rs0 += __shfl_xor_sync(0xffffffffu, rs0, 1);
    rs0 += __shfl_xor_sync(0xffffffffu, rs0, 2);
    rs1 += __shfl_xor_sync(0xffffffffu, rs1, 1);
    rs1 += __shfl_xor_sync(0xffffffffu, rs1, 2);

    if (tig == 0) {
        float* ip = g_inv + (long long)z * SEQ + q0 + wm;
        ip[gid]     = 1.0f / rs0;
        ip[gid + 8] = 1.0f / rs1;
    }
}

// ---------------------------------------------------------------------------
// Attention pass 2: per (z, 128-q tile): recompute S, p = exp(S/8)*inv,
// write p to attn (streaming stores), ctx += p @ V from registers.
// ---------------------------------------------------------------------------
struct SmemP2 {
    __half Qs[128][72];
    __half Ks[2][64][72];
    __half Vs[2][64][72];
};

__global__ __launch_bounds__(256, 2) void attn_pass2_kernel(float* __restrict__ attn)
{
    extern __shared__ char smraw[];
    SmemP2& sm = *reinterpret_cast<SmemP2*>(smraw);

    const int tid  = threadIdx.x;
    const int warp = tid >> 5;
    const int lane = tid & 31;
    const int gid  = lane >> 2;
    const int tig  = lane & 3;
    const int wm   = warp * 16;
    const int lrow = lane & 15;
    const int lcol = (lane >> 4) << 3;

    const int q0 = blockIdx.x * 128;
    const int z  = blockIdx.y;
    const int b  = z / NHEAD;
    const int h  = z % NHEAD;

    const __half* qb = g_ph + (long long)b * SEQ * D_MODEL + h * DK;
    const __half* kb = g_ph + N1 + (long long)b * SEQ * D_MODEL + h * DK;
    const __half* vb = g_ph + 2LL * N1 + (long long)b * SEQ * D_MODEL + h * DK;
    float* ab = attn + (long long)z * SEQ * SEQ;
    __half* cb = g_ctxh + (long long)b * SEQ * D_MODEL + h * DK;

    auto issueK = [&](int s, int n0) {
        #pragma unroll
        for (int it = 0; it < 2; it++) {
            const int c = tid + it * 256;
            const int key = c >> 3;
            const int ch  = (c & 7) * 8;
            cp16(&sm.Ks[s][key][ch], kb + (long long)(n0 + key) * D_MODEL + ch);
        }
    };
    auto issueV = [&](int s, int n0) {
        #pragma unroll
        for (int it = 0; it < 2; it++) {
            const int c = tid + it * 256;
            const int key = c >> 3;
            const int ch  = (c & 7) * 8;
            cp16(&sm.Vs[s][key][ch], vb + (long long)(n0 + key) * D_MODEL + ch);
        }
    };

    #pragma unroll
    for (int it = 0; it < 4; it++) {
        const int c = tid + it * 256;
        const int row = c >> 3;
        const int ch  = (c & 7) * 8;
        cp16(&sm.Qs[row][ch], qb + (long long)(q0 + row) * D_MODEL + ch);
    }
    issueK(0, 0);
    issueV(0, 0);
    cp_commit();

    // inverse rowsums for this warp's rows
    const float inv0 = g_inv[(long long)z * SEQ + q0 + wm + gid];
    const float inv1 = g_inv[(long long)z * SEQ + q0 + wm + gid + 8];

    uint32_t qf[4][4];
    float cacc[8][4] = {};

    for (int t = 0; t < 32; t++) {
        const int n0 = t * 64;
        if (t < 31) {
            issueK((t + 1) & 1, (t + 1) * 64);
            issueV((t + 1) & 1, (t + 1) * 64);
            cp_commit();
            cp_wait1();
        } else {
            cp_wait0();
        }
        __syncthreads();

        if (t == 0) {
            #pragma unroll
            for (int kk = 0; kk < 4; kk++)
                ldsm_x4(qf[kk], &sm.Qs[wm + lrow][16 * kk + lcol]);
        }

        const int bb = t & 1;

        // scores
        float sacc[8][4] = {};
        #pragma unroll
        for (int kk = 0; kk < 4; kk++) {
            uint32_t kf[4][4];
            #pragma unroll
            for (int nb = 0; nb < 4; nb++)
                ldsm_x4(kf[nb], &sm.Ks[bb][16 * nb + lrow][16 * kk + lcol]);
            #pragma unroll
            for (int nb = 0; nb < 4; nb++) {
                uint32_t b0[2] = { kf[nb][0], kf[nb][2] };
                uint32_t b1[2] = { kf[nb][1], kf[nb][3] };
                mma_f16(sacc[2 * nb],     qf[kk], b0);
                mma_f16(sacc[2 * nb + 1], qf[kk], b1);
            }
        }

        // normalize + write attn (streaming) + pack P as A-fragments
        uint32_t pa[8][2];
        {
            const int r0 = q0 + wm + gid;
            #pragma unroll
            for (int jn = 0; jn < 8; jn++) {
                const int cl = n0 + 8 * jn + 2 * tig;
                float2 e01, e23;
                e01.x = __expf(sacc[jn][0] * 0.125f) * inv0;
                e01.y = __expf(sacc[jn][1] * 0.125f) * inv0;
                e23.x = __expf(sacc[jn][2] * 0.125f) * inv1;
                e23.y = __expf(sacc[jn][3] * 0.125f) * inv1;
                stg_cs_f2(ab + (long long)r0 * SEQ + cl,       e01.x, e01.y);
                stg_cs_f2(ab + (long long)(r0 + 8) * SEQ + cl, e23.x, e23.y);
                pa[jn][0] = packh2(e01.x, e01.y);
                pa[jn][1] = packh2(e23.x, e23.y);
            }
        }

        // PV MMA from registers
        #pragma unroll
        for (int c = 0; c < 4; c++) {
            uint32_t A[4] = { pa[2 * c][0], pa[2 * c][1],
                              pa[2 * c + 1][0], pa[2 * c + 1][1] };
            uint32_t vt[4][4];
            #pragma unroll
            for (int nb = 0; nb < 4; nb++)
                ldsm_x4_t(vt[nb], &sm.Vs[bb][16 * c + lrow][16 * nb + lcol]);
            #pragma unroll
            for (int nb = 0; nb < 4; nb++) {
                mma_f16(cacc[2 * nb],     A, &vt[nb][0]);
                mma_f16(cacc[2 * nb + 1], A, &vt[nb][2]);
            }
        }
        __syncthreads();
    }

    {
        const int row = q0 + wm + gid;
        #pragma unroll
        for (int jn = 0; jn < 8; jn++) {
            const int col = 8 * jn + 2 * tig;
            *(uint32_t*)(cb + (long long)row * D_MODEL + col)       = packh2(cacc[jn][0], cacc[jn][1]);
            *(uint32_t*)(cb + (long long)(row + 8) * D_MODEL + col) = packh2(cacc[jn][2], cacc[jn][3]);
        }
    }
}

// ---------------------------------------------------------------------------
extern "C" void kernel_launch(void* const* d_in, const int* in_sizes, int n_in,
                              void* d_out, int out_size)
{
    const float* q   = (const float*)d_in[0];
    const float* k   = (const float*)d_in[1];
    const float* v   = (const float*)d_in[2];
    const float* w_q = (const float*)d_in[3];
    const float* b_q = (const float*)d_in[4];
    const float* w_k = (const float*)d_in[5];
    const float* b_k = (const float*)d_in[6];
    const float* w_v = (const float*)d_in[7];
    const float* b_v = (const float*)d_in[8];
    const float* w_o = (const float*)d_in[9];
    const float* b_o = (const float*)d_in[10];

    float* gattn;
    cudaGetSymbolAddress((void**)&gattn, g_attn);

    float* outp = (float*)d_out;
    const long long OUT_ELEMS  = (long long)MROWS * D_MODEL;
    const long long ATTN_ELEMS = (long long)BATCH * NHEAD * SEQ * SEQ;
    float* attn = ((long long)out_size >= OUT_ELEMS + ATTN_ELEMS) ? (outp + OUT_ELEMS)
                                                                  : gattn;

    // 0. convert inputs + weights to half
    convert_kernel<<<1024, 256>>>(q, k, v, w_q, w_k, w_v, w_o);

    // 1. QKV projections (half in, half out), 128x128 tiles
    {
        const dim3 grid(D_MODEL / 128, MROWS / 128, 3);
        qkv_proj_kernel<<<grid, 256>>>(b_q, b_k, b_v);
    }

    // 2a. attention pass 1: rowsums (occupancy 3)
    {
        static int s1 = 0;
        if (!s1) {
            cudaFuncSetAttribute(attn_pass1_kernel,
                                 cudaFuncAttributeMaxDynamicSharedMemorySize, (int)sizeof(SmemP1));
            s1 = 1;
        }
        const dim3 grid(SEQ / 128, BATCH * NHEAD);
        attn_pass1_kernel<<<grid, 256, sizeof(SmemP1)>>>();
    }

    // 2b. attention pass 2: normalize + attn write + PV
    {
        static int s2 = 0;
        if (!s2) {
            cudaFuncSetAttribute(attn_pass2_kernel,
                                 cudaFuncAttributeMaxDynamicSharedMemorySize, (int)sizeof(SmemP2));
            s2 = 1;
        }
        const dim3 grid(SEQ / 128, BATCH * NHEAD);
        attn_pass2_kernel<<<grid, 256, sizeof(SmemP2)>>>(attn);
    }

    // 3. output projection (fp32 out), 128x128 tiles
    {
        const dim3 grid(D_MODEL / 128, MROWS / 128, 1);
        out_proj_kernel<<<grid, 256>>>(b_o, outp);
    }
}

// round 15
// speedup vs baseline: 1.3424x; 1.0910x over previous
#include <cuda_runtime.h>
#include <cuda_fp16.h>
#include <math.h>
#include <stdint.h>

// Problem constants
#define D_MODEL 768
#define NHEAD   12
#define DK      64
#define BATCH   2
#define SEQ     2048
#define MROWS   (BATCH*SEQ)   // 4096
#define N1 (MROWS*D_MODEL)    // 3,145,728
#define N2 (D_MODEL*D_MODEL)  // 589,824

// exp(s/8) = 2^(s * 0.125 * log2(e)); fold this into W_q/b_q.
#define QSCALE 0.18033688011112042f

// Scratch in device globals (allocation-free rule)
__device__ __half g_xh[3 * N1];    // half copies of q,k,v inputs
__device__ __half g_wh[4 * N2];    // half copies of w_q(scaled),w_k,w_v,w_o
__device__ __half g_ph[3 * N1];    // projected qh(scaled), kh, vh (half)
__device__ __half g_ctxh[N1];      // attention context (half)
__device__ float  g_inv[BATCH * NHEAD * SEQ];
__device__ float  g_attn[(size_t)BATCH * NHEAD * SEQ * SEQ]; // fallback

// ---------------------------------------------------------------------------
// Low-level helpers
// ---------------------------------------------------------------------------
__device__ __forceinline__ uint32_t packh2(float x, float y) {
    __half2 h = __floats2half2_rn(x, y);
    return *reinterpret_cast<uint32_t*>(&h);
}

__device__ __forceinline__ float ex2f(float x) {
    float y;
    asm("ex2.approx.ftz.f32 %0, %1;" : "=f"(y) : "f"(x));
    return y;
}

__device__ __forceinline__ void mma_f16(float* d, const uint32_t* a, const uint32_t* b) {
    asm volatile(
        "mma.sync.aligned.m16n8k16.row.col.f32.f16.f16.f32 "
        "{%0,%1,%2,%3}, {%4,%5,%6,%7}, {%8,%9}, {%0,%1,%2,%3};\n"
        : "+f"(d[0]), "+f"(d[1]), "+f"(d[2]), "+f"(d[3])
        : "r"(a[0]), "r"(a[1]), "r"(a[2]), "r"(a[3]), "r"(b[0]), "r"(b[1]));
}

__device__ __forceinline__ void ldsm_x4(uint32_t* r, const void* p) {
    uint32_t a = (uint32_t)__cvta_generic_to_shared(p);
    asm volatile("ldmatrix.sync.aligned.m8n8.x4.shared.b16 {%0,%1,%2,%3}, [%4];"
                 : "=r"(r[0]), "=r"(r[1]), "=r"(r[2]), "=r"(r[3]) : "r"(a));
}
__device__ __forceinline__ void ldsm_x4_t(uint32_t* r, const void* p) {
    uint32_t a = (uint32_t)__cvta_generic_to_shared(p);
    asm volatile("ldmatrix.sync.aligned.m8n8.x4.trans.shared.b16 {%0,%1,%2,%3}, [%4];"
                 : "=r"(r[0]), "=r"(r[1]), "=r"(r[2]), "=r"(r[3]) : "r"(a));
}

__device__ __forceinline__ void cp16(void* s, const void* g) {
    uint32_t a = (uint32_t)__cvta_generic_to_shared(s);
    asm volatile("cp.async.cg.shared.global [%0], [%1], 16;" :: "r"(a), "l"(g));
}
__device__ __forceinline__ void cp_commit() {
    asm volatile("cp.async.commit_group;" ::);
}
__device__ __forceinline__ void cp_wait1() {
    asm volatile("cp.async.wait_group 1;" ::);
}
__device__ __forceinline__ void cp_wait0() {
    asm volatile("cp.async.wait_group 0;" ::);
}

__device__ __forceinline__ void stg_cs_f2(float* p, float x, float y) {
    asm volatile("st.global.cs.v2.f32 [%0], {%1,%2};" :: "l"(p), "f"(x), "f"(y) : "memory");
}

// ---------------------------------------------------------------------------
// Convert kernel: fp32 inputs/weights -> half scratch; w_q scaled by QSCALE.
// ---------------------------------------------------------------------------
__global__ void convert_kernel(const float* __restrict__ q, const float* __restrict__ k,
                               const float* __restrict__ v,
                               const float* __restrict__ wq, const float* __restrict__ wk,
                               const float* __restrict__ wv, const float* __restrict__ wo)
{
    const long long TOT4 = (3LL * N1 + 4LL * N2) / 4;
    for (long long i4 = blockIdx.x * blockDim.x + threadIdx.x; i4 < TOT4;
         i4 += (long long)gridDim.x * blockDim.x) {
        const long long e = i4 * 4;
        const float* src;
        __half* dst;
        float scale = 1.0f;
        if (e < 3LL * N1) {
            const int w = (int)(e / N1);
            const long long off = e - (long long)w * N1;
            src = (w == 0 ? q : w == 1 ? k : v) + off;
            dst = g_xh + e;
        } else {
            const long long e2 = e - 3LL * N1;
            const int w = (int)(e2 / N2);
            const long long off = e2 - (long long)w * N2;
            src = (w == 0 ? wq : w == 1 ? wk : w == 2 ? wv : wo) + off;
            dst = g_wh + e2;
            if (w == 0) scale = QSCALE;
        }
        const float4 f = *(const float4*)src;
        uint2 u;
        u.x = packh2(f.x * scale, f.y * scale);
        u.y = packh2(f.z * scale, f.w * scale);
        *(uint2*)dst = u;
    }
}

// ---------------------------------------------------------------------------
// 768-K GEMM body, 128x128 tile (for QKV): C = A @ W + bias*bscale
// BK=32, cp.async double-buffer, ldmatrix. 8 warps (4M x 2N), 32x64 warp tile.
// ---------------------------------------------------------------------------
__device__ __forceinline__ void gemm_body_128(const __half* __restrict__ A,
                                              const __half* __restrict__ W,
                                              const float* __restrict__ bias,
                                              float bscale,
                                              __half* __restrict__ C)
{
    __shared__ alignas(16) __half As[2][128][40];
    __shared__ alignas(16) __half Ws[2][32][136];

    const int tid  = threadIdx.x;
    const int warp = tid >> 5;
    const int lane = tid & 31;
    const int gid  = lane >> 2;
    const int tig  = lane & 3;
    const int wm   = (warp & 3) * 32;
    const int wn   = (warp >> 2) * 64;
    const int lrow = lane & 15;
    const int lcol = (lane >> 4) << 3;

    const int m0 = blockIdx.y * 128;
    const int n0 = blockIdx.x * 128;
    const __half* Ab = A + (long long)m0 * D_MODEL;
    const __half* Wb = W + n0;

    auto issueA = [&](int s, int k0) {
        #pragma unroll
        for (int it = 0; it < 2; it++) {
            const int c = tid + it * 256;
            const int row = c >> 2;
            const int ch  = (c & 3) * 8;
            cp16(&As[s][row][ch], Ab + (long long)row * D_MODEL + k0 + ch);
        }
    };
    auto issueW = [&](int s, int k0) {
        #pragma unroll
        for (int it = 0; it < 2; it++) {
            const int c = tid + it * 256;
            const int row = c >> 4;
            const int ch  = (c & 15) * 8;
            cp16(&Ws[s][row][ch], Wb + (long long)(k0 + row) * D_MODEL + ch);
        }
    };

    issueA(0, 0);
    issueW(0, 0);
    cp_commit();

    float acc[2][8][4] = {};

    for (int s = 0; s < 24; s++) {
        if (s < 23) {
            issueA((s + 1) & 1, (s + 1) * 32);
            issueW((s + 1) & 1, (s + 1) * 32);
            cp_commit();
            cp_wait1();
        } else {
            cp_wait0();
        }
        __syncthreads();

        const int bb = s & 1;
        #pragma unroll
        for (int kk = 0; kk < 32; kk += 16) {
            uint32_t af[2][4], bt[4][4];
            ldsm_x4(af[0], &As[bb][wm + lrow][kk + lcol]);
            ldsm_x4(af[1], &As[bb][wm + 16 + lrow][kk + lcol]);
            #pragma unroll
            for (int jj = 0; jj < 4; jj++)
                ldsm_x4_t(bt[jj], &Ws[bb][kk + lrow][wn + 16 * jj + lcol]);
            #pragma unroll
            for (int i = 0; i < 2; i++)
                #pragma unroll
                for (int jj = 0; jj < 4; jj++) {
                    mma_f16(acc[i][2 * jj],     af[i], &bt[jj][0]);
                    mma_f16(acc[i][2 * jj + 1], af[i], &bt[jj][2]);
                }
        }
        __syncthreads();
    }

    #pragma unroll
    for (int i = 0; i < 2; i++) {
        const int row = m0 + wm + 16 * i + gid;
        #pragma unroll
        for (int j = 0; j < 8; j++) {
            const int col = n0 + wn + 8 * j + 2 * tig;
            const float b0 = bias[col] * bscale;
            const float b1 = bias[col + 1] * bscale;
            *(uint32_t*)(C + (long long)row * D_MODEL + col) =
                packh2(acc[i][j][0] + b0, acc[i][j][1] + b1);
            *(uint32_t*)(C + (long long)(row + 8) * D_MODEL + col) =
                packh2(acc[i][j][2] + b0, acc[i][j][3] + b1);
        }
    }
}

__global__ __launch_bounds__(256, 2) void qkv_proj_kernel(
    const float* __restrict__ bq, const float* __restrict__ bk, const float* __restrict__ bv)
{
    const int z = blockIdx.z;
    const float* bias = (z == 0) ? bq : (z == 1) ? bk : bv;
    const float bscale = (z == 0) ? QSCALE : 1.0f;
    gemm_body_128(g_xh + (long long)z * N1, g_wh + (long long)z * N2,
                  bias, bscale, g_ph + (long long)z * N1);
}

// ---------------------------------------------------------------------------
// 768-K GEMM body, 128x64 tile (for out-proj, occ 3): C(f32) = A @ W + bias
// Round-7 configuration: 8 warps (4M x 2N), 32x32 warp tile.
// ---------------------------------------------------------------------------
__global__ __launch_bounds__(256, 3) void out_proj_kernel(
    const float* __restrict__ bias, float* __restrict__ C)
{
    __shared__ alignas(16) __half As[2][128][40];
    __shared__ alignas(16) __half Ws[2][32][72];

    const __half* A = g_ctxh;
    const __half* W = g_wh + 3LL * N2;

    const int tid  = threadIdx.x;
    const int warp = tid >> 5;
    const int lane = tid & 31;
    const int gid  = lane >> 2;
    const int tig  = lane & 3;
    const int wm   = (warp & 3) * 32;
    const int wn   = (warp >> 2) * 32;
    const int lrow = lane & 15;
    const int lcol = (lane >> 4) << 3;

    const int m0 = blockIdx.y * 128;
    const int n0 = blockIdx.x * 64;
    const __half* Ab = A + (long long)m0 * D_MODEL;
    const __half* Wb = W + n0;

    auto issueA = [&](int s, int k0) {
        #pragma unroll
        for (int it = 0; it < 2; it++) {
            const int c = tid + it * 256;
            const int row = c >> 2;
            const int ch  = (c & 3) * 8;
            cp16(&As[s][row][ch], Ab + (long long)row * D_MODEL + k0 + ch);
        }
    };
    auto issueW = [&](int s, int k0) {
        const int row = tid >> 3;
        const int ch  = (tid & 7) * 8;
        cp16(&Ws[s][row][ch], Wb + (long long)(k0 + row) * D_MODEL + ch);
    };

    issueA(0, 0);
    issueW(0, 0);
    cp_commit();

    float acc[2][4][4] = {};

    for (int s = 0; s < 24; s++) {
        if (s < 23) {
            issueA((s + 1) & 1, (s + 1) * 32);
            issueW((s + 1) & 1, (s + 1) * 32);
            cp_commit();
            cp_wait1();
        } else {
            cp_wait0();
        }
        __syncthreads();

        const int bb = s & 1;
        #pragma unroll
        for (int kk = 0; kk < 32; kk += 16) {
            uint32_t af[2][4], bt[2][4];
            ldsm_x4(af[0], &As[bb][wm + lrow][kk + lcol]);
            ldsm_x4(af[1], &As[bb][wm + 16 + lrow][kk + lcol]);
            ldsm_x4_t(bt[0], &Ws[bb][kk + lrow][wn + lcol]);
            ldsm_x4_t(bt[1], &Ws[bb][kk + lrow][wn + 16 + lcol]);
            #pragma unroll
            for (int i = 0; i < 2; i++) {
                mma_f16(acc[i][0], af[i], &bt[0][0]);
                mma_f16(acc[i][1], af[i], &bt[0][2]);
                mma_f16(acc[i][2], af[i], &bt[1][0]);
                mma_f16(acc[i][3], af[i], &bt[1][2]);
            }
        }
        __syncthreads();
    }

    #pragma unroll
    for (int i = 0; i < 2; i++) {
        const int row = m0 + wm + 16 * i + gid;
        #pragma unroll
        for (int j = 0; j < 4; j++) {
            const int col = n0 + wn + 8 * j + 2 * tig;
            const float b0 = bias[col];
            const float b1 = bias[col + 1];
            *(float2*)(C + (long long)row * D_MODEL + col) =
                make_float2(acc[i][j][0] + b0, acc[i][j][1] + b1);
            *(float2*)(C + (long long)(row + 8) * D_MODEL + col) =
                make_float2(acc[i][j][2] + b0, acc[i][j][3] + b1);
        }
    }
}

// ---------------------------------------------------------------------------
// Attention pass 1: rowsums of 2^S -> g_inv. 8 warps x m16 slabs, occ 3.
// Q is pre-scaled so exp is a single ex2.
// ---------------------------------------------------------------------------
struct SmemP1 {
    __half Qs[128][72];
    __half Ks[2][64][72];
};

__global__ __launch_bounds__(256, 3) void attn_pass1_kernel()
{
    extern __shared__ char smraw[];
    SmemP1& sm = *reinterpret_cast<SmemP1*>(smraw);

    const int tid  = threadIdx.x;
    const int warp = tid >> 5;
    const int lane = tid & 31;
    const int gid  = lane >> 2;
    const int tig  = lane & 3;
    const int wm   = warp * 16;
    const int lrow = lane & 15;
    const int lcol = (lane >> 4) << 3;

    const int q0 = blockIdx.x * 128;
    const int z  = blockIdx.y;
    const int b  = z / NHEAD;
    const int h  = z % NHEAD;

    const __half* qb = g_ph + (long long)b * SEQ * D_MODEL + h * DK;
    const __half* kb = g_ph + N1 + (long long)b * SEQ * D_MODEL + h * DK;

    auto issueK = [&](int s, int n0) {
        #pragma unroll
        for (int it = 0; it < 2; it++) {
            const int c = tid + it * 256;
            const int key = c >> 3;
            const int ch  = (c & 7) * 8;
            cp16(&sm.Ks[s][key][ch], kb + (long long)(n0 + key) * D_MODEL + ch);
        }
    };

    #pragma unroll
    for (int it = 0; it < 4; it++) {
        const int c = tid + it * 256;
        const int row = c >> 3;
        const int ch  = (c & 7) * 8;
        cp16(&sm.Qs[row][ch], qb + (long long)(q0 + row) * D_MODEL + ch);
    }
    issueK(0, 0);
    cp_commit();

    uint32_t qf[4][4];
    float rs0 = 0.f, rs1 = 0.f;

    for (int t = 0; t < 32; t++) {
        if (t < 31) {
            issueK((t + 1) & 1, (t + 1) * 64);
            cp_commit();
            cp_wait1();
        } else {
            cp_wait0();
        }
        __syncthreads();

        if (t == 0) {
            #pragma unroll
            for (int kk = 0; kk < 4; kk++)
                ldsm_x4(qf[kk], &sm.Qs[wm + lrow][16 * kk + lcol]);
        }

        const int bb = t & 1;
        float sacc[8][4] = {};
        #pragma unroll
        for (int kk = 0; kk < 4; kk++) {
            uint32_t kf[4][4];
            #pragma unroll
            for (int nb = 0; nb < 4; nb++)
                ldsm_x4(kf[nb], &sm.Ks[bb][16 * nb + lrow][16 * kk + lcol]);
            #pragma unroll
            for (int nb = 0; nb < 4; nb++) {
                uint32_t b0[2] = { kf[nb][0], kf[nb][2] };
                uint32_t b1[2] = { kf[nb][1], kf[nb][3] };
                mma_f16(sacc[2 * nb],     qf[kk], b0);
                mma_f16(sacc[2 * nb + 1], qf[kk], b1);
            }
        }

        #pragma unroll
        for (int jn = 0; jn < 8; jn++) {
            rs0 += ex2f(sacc[jn][0]) + ex2f(sacc[jn][1]);
            rs1 += ex2f(sacc[jn][2]) + ex2f(sacc[jn][3]);
        }
        __syncthreads();
    }

    rs0 += __shfl_xor_sync(0xffffffffu, rs0, 1);
    rs0 += __shfl_xor_sync(0xffffffffu, rs0, 2);
    rs1 += __shfl_xor_sync(0xffffffffu, rs1, 1);
    rs1 += __shfl_xor_sync(0xffffffffu, rs1, 2);

    if (tig == 0) {
        float* ip = g_inv + (long long)z * SEQ + q0 + wm;
        ip[gid]     = 1.0f / rs0;
        ip[gid + 8] = 1.0f / rs1;
    }
}

// ---------------------------------------------------------------------------
// Attention pass 2: recompute S, p = 2^S * inv, write p (streaming),
// ctx += p @ V from registers.
// ---------------------------------------------------------------------------
struct SmemP2 {
    __half Qs[128][72];
    __half Ks[2][64][72];
    __half Vs[2][64][72];
};

__global__ __launch_bounds__(256, 2) void attn_pass2_kernel(float* __restrict__ attn)
{
    extern __shared__ char smraw[];
    SmemP2& sm = *reinterpret_cast<SmemP2*>(smraw);

    const int tid  = threadIdx.x;
    const int warp = tid >> 5;
    const int lane = tid & 31;
    const int gid  = lane >> 2;
    const int tig  = lane & 3;
    const int wm   = warp * 16;
    const int lrow = lane & 15;
    const int lcol = (lane >> 4) << 3;

    const int q0 = blockIdx.x * 128;
    const int z  = blockIdx.y;
    const int b  = z / NHEAD;
    const int h  = z % NHEAD;

    const __half* qb = g_ph + (long long)b * SEQ * D_MODEL + h * DK;
    const __half* kb = g_ph + N1 + (long long)b * SEQ * D_MODEL + h * DK;
    const __half* vb = g_ph + 2LL * N1 + (long long)b * SEQ * D_MODEL + h * DK;
    float* ab = attn + (long long)z * SEQ * SEQ;
    __half* cb = g_ctxh + (long long)b * SEQ * D_MODEL + h * DK;

    auto issueK = [&](int s, int n0) {
        #pragma unroll
        for (int it = 0; it < 2; it++) {
            const int c = tid + it * 256;
            const int key = c >> 3;
            const int ch  = (c & 7) * 8;
            cp16(&sm.Ks[s][key][ch], kb + (long long)(n0 + key) * D_MODEL + ch);
        }
    };
    auto issueV = [&](int s, int n0) {
        #pragma unroll
        for (int it = 0; it < 2; it++) {
            const int c = tid + it * 256;
            const int key = c >> 3;
            const int ch  = (c & 7) * 8;
            cp16(&sm.Vs[s][key][ch], vb + (long long)(n0 + key) * D_MODEL + ch);
        }
    };

    #pragma unroll
    for (int it = 0; it < 4; it++) {
        const int c = tid + it * 256;
        const int row = c >> 3;
        const int ch  = (c & 7) * 8;
        cp16(&sm.Qs[row][ch], qb + (long long)(q0 + row) * D_MODEL + ch);
    }
    issueK(0, 0);
    issueV(0, 0);
    cp_commit();

    const float inv0 = g_inv[(long long)z * SEQ + q0 + wm + gid];
    const float inv1 = g_inv[(long long)z * SEQ + q0 + wm + gid + 8];

    uint32_t qf[4][4];
    float cacc[8][4] = {};

    for (int t = 0; t < 32; t++) {
        const int n0 = t * 64;
        if (t < 31) {
            issueK((t + 1) & 1, (t + 1) * 64);
            issueV((t + 1) & 1, (t + 1) * 64);
            cp_commit();
            cp_wait1();
        } else {
            cp_wait0();
        }
        __syncthreads();

        if (t == 0) {
            #pragma unroll
            for (int kk = 0; kk < 4; kk++)
                ldsm_x4(qf[kk], &sm.Qs[wm + lrow][16 * kk + lcol]);
        }

        const int bb = t & 1;

        // scores
        float sacc[8][4] = {};
        #pragma unroll
        for (int kk = 0; kk < 4; kk++) {
            uint32_t kf[4][4];
            #pragma unroll
            for (int nb = 0; nb < 4; nb++)
                ldsm_x4(kf[nb], &sm.Ks[bb][16 * nb + lrow][16 * kk + lcol]);
            #pragma unroll
            for (int nb = 0; nb < 4; nb++) {
                uint32_t b0[2] = { kf[nb][0], kf[nb][2] };
                uint32_t b1[2] = { kf[nb][1], kf[nb][3] };
                mma_f16(sacc[2 * nb],     qf[kk], b0);
                mma_f16(sacc[2 * nb + 1], qf[kk], b1);
            }
        }

        // normalize + write attn (streaming) + pack P as A-fragments
        uint32_t pa[8][2];
        {
            const int r0 = q0 + wm + gid;
            #pragma unroll
            for (int jn = 0; jn < 8; jn++) {
                const int cl = n0 + 8 * jn + 2 * tig;
                float2 e01, e23;
                e01.x = ex2f(sacc[jn][0]) * inv0;
                e01.y = ex2f(sacc[jn][1]) * inv0;
                e23.x = ex2f(sacc[jn][2]) * inv1;
                e23.y = ex2f(sacc[jn][3]) * inv1;
                stg_cs_f2(ab + (long long)r0 * SEQ + cl,       e01.x, e01.y);
                stg_cs_f2(ab + (long long)(r0 + 8) * SEQ + cl, e23.x, e23.y);
                pa[jn][0] = packh2(e01.x, e01.y);
                pa[jn][1] = packh2(e23.x, e23.y);
            }
        }

        // PV MMA from registers
        #pragma unroll
        for (int c = 0; c < 4; c++) {
            uint32_t A[4] = { pa[2 * c][0], pa[2 * c][1],
                              pa[2 * c + 1][0], pa[2 * c + 1][1] };
            uint32_t vt[4][4];
            #pragma unroll
            for (int nb = 0; nb < 4; nb++)
                ldsm_x4_t(vt[nb], &sm.Vs[bb][16 * c + lrow][16 * nb + lcol]);
            #pragma unroll
            for (int nb = 0; nb < 4; nb++) {
                mma_f16(cacc[2 * nb],     A, &vt[nb][0]);
                mma_f16(cacc[2 * nb + 1], A, &vt[nb][2]);
            }
        }
        __syncthreads();
    }

    {
        const int row = q0 + wm + gid;
        #pragma unroll
        for (int jn = 0; jn < 8; jn++) {
            const int col = 8 * jn + 2 * tig;
            *(uint32_t*)(cb + (long long)row * D_MODEL + col)       = packh2(cacc[jn][0], cacc[jn][1]);
            *(uint32_t*)(cb + (long long)(row + 8) * D_MODEL + col) = packh2(cacc[jn][2], cacc[jn][3]);
        }
    }
}

// ---------------------------------------------------------------------------
extern "C" void kernel_launch(void* const* d_in, const int* in_sizes, int n_in,
                              void* d_out, int out_size)
{
    const float* q   = (const float*)d_in[0];
    const float* k   = (const float*)d_in[1];
    const float* v   = (const float*)d_in[2];
    const float* w_q = (const float*)d_in[3];
    const float* b_q = (const float*)d_in[4];
    const float* w_k = (const float*)d_in[5];
    const float* b_k = (const float*)d_in[6];
    const float* w_v = (const float*)d_in[7];
    const float* b_v = (const float*)d_in[8];
    const float* w_o = (const float*)d_in[9];
    const float* b_o = (const float*)d_in[10];

    float* gattn;
    cudaGetSymbolAddress((void**)&gattn, g_attn);

    float* outp = (float*)d_out;
    const long long OUT_ELEMS  = (long long)MROWS * D_MODEL;
    const long long ATTN_ELEMS = (long long)BATCH * NHEAD * SEQ * SEQ;
    float* attn = ((long long)out_size >= OUT_ELEMS + ATTN_ELEMS) ? (outp + OUT_ELEMS)
                                                                  : gattn;

    // 0. convert inputs + weights to half (w_q scaled by QSCALE)
    convert_kernel<<<1024, 256>>>(q, k, v, w_q, w_k, w_v, w_o);

    // 1. QKV projections, 128x128 tiles (Q output pre-scaled)
    {
        const dim3 grid(D_MODEL / 128, MROWS / 128, 3);
        qkv_proj_kernel<<<grid, 256>>>(b_q, b_k, b_v);
    }

    // 2a. attention pass 1: rowsums (occ 3)
    {
        static int s1 = 0;
        if (!s1) {
            cudaFuncSetAttribute(attn_pass1_kernel,
                                 cudaFuncAttributeMaxDynamicSharedMemorySize, (int)sizeof(SmemP1));
            s1 = 1;
        }
        const dim3 grid(SEQ / 128, BATCH * NHEAD);
        attn_pass1_kernel<<<grid, 256, sizeof(SmemP1)>>>();
    }

    // 2b. attention pass 2: normalize + attn write + PV
    {
        static int s2 = 0;
        if (!s2) {
            cudaFuncSetAttribute(attn_pass2_kernel,
                                 cudaFuncAttributeMaxDynamicSharedMemorySize, (int)sizeof(SmemP2));
            s2 = 1;
        }
        const dim3 grid(SEQ / 128, BATCH * NHEAD);
        attn_pass2_kernel<<<grid, 256, sizeof(SmemP2)>>>(attn);
    }

    // 3. output projection, 128x64 tiles (occ 3, fp32 out)
    {
        const dim3 grid(D_MODEL / 64, MROWS / 128, 1);
        out_proj_kernel<<<grid, 256>>>(b_o, outp);
    }
}